// round 7
// baseline (speedup 1.0000x reference)
#include <cuda_runtime.h>
#include <cuda_bf16.h>
#include <math.h>
#include <stdint.h>

#define NN      50000
#define IN_F    256
#define HID     128
#define HEADS   4
#define EE      800000
#define COLS    (HEADS * HID)          // 512
#define ALPHA_L 0.2f
#define INV_SCALE 0.04419417382415922f // 1/sqrt(512)
#define LN_EPS  1e-6f

#define M_TILES ((NN + 127) / 128)     // 391
#define M_PAD   (M_TILES * 128)        // 50048

#define PREP_A_BLOCKS (M_PAD * (IN_F / 4) / 256)   // 12512 exactly
#define ZERO_BLOCKS   ((NN * HEADS + 255) / 256)   // 782
#define PREPB_BLOCKS  ((COLS * IN_F) / 256)        // 512

// ---------------- scratch (static device memory; no allocations) ------------
__device__ float          g_X[(size_t)NN * COLS];     // 102.4 MB
__device__ float          g_s1[NN * HEADS];
__device__ float          g_s2[NN * HEADS];
__device__ __nv_bfloat16  g_Ahi[(size_t)M_PAD * IN_F];
__device__ __nv_bfloat16  g_Alo[(size_t)M_PAD * IN_F];
__device__ __nv_bfloat16  g_Bhi[COLS * IN_F];         // W split hi (512x256)
__device__ __nv_bfloat16  g_Blo[COLS * IN_F];
__device__ float4         g_es[EE];
__device__ int            g_dsts[EE];
__device__ int            g_deg[NN];
__device__ int            g_rowptr[NN + 1];
__device__ int            g_cursor[NN];
__device__ int            g_is64;

// ---------------- helpers ---------------------------------------------------
__device__ __forceinline__ int load_edge(const void* e, long long idx) {
    if (g_is64) return (int)((const long long*)e)[idx];
    return ((const int*)e)[idx];
}
__device__ __forceinline__ uint32_t smem_u32(const void* p) {
    uint32_t a;
    asm("{ .reg .u64 t; cvta.to.shared.u64 t, %1; cvt.u32.u64 %0, t; }"
        : "=r"(a) : "l"(p));
    return a;
}
__device__ __forceinline__ void ldsm4(uint32_t* r, uint32_t addr) {
    asm volatile("ldmatrix.sync.aligned.m8n8.x4.shared.b16 {%0,%1,%2,%3}, [%4];"
                 : "=r"(r[0]), "=r"(r[1]), "=r"(r[2]), "=r"(r[3]) : "r"(addr));
}
__device__ __forceinline__ void mma_bf16(float* c, const uint32_t* a,
                                         const uint32_t* b) {
    asm volatile(
        "mma.sync.aligned.m16n8k16.row.col.f32.bf16.bf16.f32 "
        "{%0,%1,%2,%3}, {%4,%5,%6,%7}, {%8,%9}, {%0,%1,%2,%3};"
        : "+f"(c[0]), "+f"(c[1]), "+f"(c[2]), "+f"(c[3])
        : "r"(a[0]), "r"(a[1]), "r"(a[2]), "r"(a[3]), "r"(b[0]), "r"(b[1]));
}
__device__ __forceinline__ void cp16(uint32_t saddr, const void* gptr) {
    asm volatile("cp.async.cg.shared.global [%0], [%1], 16;"
                 :: "r"(saddr), "l"(gptr));
}
__device__ __forceinline__ void cp_commit() {
    asm volatile("cp.async.commit_group;" ::: "memory");
}
template <int N>
__device__ __forceinline__ void cp_wait() {
    asm volatile("cp.async.wait_group %0;" :: "n"(N) : "memory");
}
// SW64 swizzle for 64B rows: chunk16 index ^= (row>>1)&3
__device__ __forceinline__ uint32_t swz64(uint32_t row, uint32_t cbyte) {
    return row * 64 + (cbyte ^ (((row >> 1) & 3) << 4));
}
__device__ __forceinline__ uint32_t pack2(__nv_bfloat16 a, __nv_bfloat16 b) {
    return (uint32_t)__bfloat16_as_ushort(a) | ((uint32_t)__bfloat16_as_ushort(b) << 16);
}

// gemm smem: 2 stages x 24KB (A hi 8K, A lo 8K, B hi 4K, B lo 4K) = 48KB static
#define ST_A_HI 0
#define ST_A_LO 8192
#define ST_B_HI 16384
#define ST_B_LO 20480
#define STAGE   24576
#define NCHUNK  8                      // 256 / 32

// ---------------- merged prep kernel -----------------------------------------
// Fuses: edge-dtype detect, s1/s2/deg zeroing, W split (prep_b), emb split
// (prep_a). All four are mutually independent.
__global__ void prep_kernel(const float* __restrict__ emb,
                            const float* __restrict__ W,
                            const int*   __restrict__ edge_raw)
{
    const int b   = blockIdx.x;
    const int tid = threadIdx.x;

    // ---- detect (block 0, warp 0) ----
    if (b == 0 && tid < 32) {
        int bad = 0;
        for (int i = tid; i < 2048; i += 32)
            if (edge_raw[2 * i + 1] != 0) bad = 1;
        unsigned m = __ballot_sync(0xffffffffu, bad);
        if (tid == 0) g_is64 = (m == 0);
    }
    // ---- zero s1/s2/deg ----
    if (b < ZERO_BLOCKS) {
        int i = b * 256 + tid;
        if (i < NN * HEADS) { g_s1[i] = 0.f; g_s2[i] = 0.f; }
        if (i < NN) g_deg[i] = 0;
    }
    // ---- W split ----
    if (b < PREPB_BLOCKS) {
        int i = b * 256 + tid;
        float w = W[i];
        __nv_bfloat16 hi = __float2bfloat16(w);
        __nv_bfloat16 lo = __float2bfloat16(w - __bfloat162float(hi));
        g_Bhi[i] = hi;
        g_Blo[i] = lo;
    }
    // ---- emb split (every block) ----
    {
        int i = b * 256 + tid;                      // float4 granularity
        int row = i >> 6;
        int c4  = i & 63;
        float4 v = make_float4(0.f, 0.f, 0.f, 0.f);
        if (row < NN && row != 0)
            v = *reinterpret_cast<const float4*>(emb + (size_t)row * IN_F + c4 * 4);
        __nv_bfloat16 h0 = __float2bfloat16(v.x), h1 = __float2bfloat16(v.y);
        __nv_bfloat16 h2 = __float2bfloat16(v.z), h3 = __float2bfloat16(v.w);
        __nv_bfloat16 l0 = __float2bfloat16(v.x - __bfloat162float(h0));
        __nv_bfloat16 l1 = __float2bfloat16(v.y - __bfloat162float(h1));
        __nv_bfloat16 l2 = __float2bfloat16(v.z - __bfloat162float(h2));
        __nv_bfloat16 l3 = __float2bfloat16(v.w - __bfloat162float(h3));
        size_t off = (size_t)row * IN_F + c4 * 4;
        *reinterpret_cast<uint2*>(g_Ahi + off) = make_uint2(pack2(h0, h1), pack2(h2, h3));
        *reinterpret_cast<uint2*>(g_Alo + off) = make_uint2(pack2(l0, l1), pack2(l2, l3));
    }
}

// ---------------- split-bf16 HMMA GEMM, cp.async double-buffered -------------
__global__ __launch_bounds__(256, 2) void gemm_mma_kernel(
    const float* __restrict__ bias, const float* __restrict__ a_attn)
{
    __shared__ char smem[2 * STAGE];
    const uint32_t sb = smem_u32(smem);
    const int tid  = threadIdx.x;
    const int wid  = tid >> 5;
    const int lane = tid & 31;
    const int wm   = wid & 3;        // 0..3 (rows)
    const int wn   = wid >> 2;       // 0..1 (cols)
    const int bm   = blockIdx.x * 128;
    const int bn   = blockIdx.y * 64;
    const int h    = bn >> 7;        // head

    float acc[2][4][4];
#pragma unroll
    for (int i = 0; i < 2; i++)
#pragma unroll
        for (int j = 0; j < 4; j++)
#pragma unroll
            for (int r = 0; r < 4; r++) acc[i][j][r] = 0.f;

    const int a_row0 = tid >> 2;
    const int a_c16  = tid & 3;
    const int b_row  = tid >> 2;
    const int arow = wm * 32 + (lane & 15);
    const uint32_t a_klane = (uint32_t)((lane >> 4) << 4);
    const uint32_t a_xor   = (uint32_t)(((arow >> 1) & 3) << 4);
    const int m4   = lane >> 3;
    const int brow = wn * 32 + ((m4 >> 1) << 3) + (lane & 7);
    const uint32_t b_klane = (uint32_t)((m4 & 1) << 4);
    const uint32_t b_xor   = (uint32_t)(((brow >> 1) & 3) << 4);

    auto load_stage = [&](int kc, int buf) {
        uint32_t s0 = sb + buf * STAGE;
#pragma unroll
        for (int l = 0; l < 2; l++) {
            int row = a_row0 + 64 * l;
            uint32_t so = swz64(row, a_c16 * 16);
            size_t gsrc = (size_t)(bm + row) * IN_F + kc * 32 + a_c16 * 8;
            cp16(s0 + ST_A_HI + so, g_Ahi + gsrc);
            cp16(s0 + ST_A_LO + so, g_Alo + gsrc);
        }
        {
            uint32_t so = swz64(b_row, a_c16 * 16);
            size_t gsrc = (size_t)(bn + b_row) * IN_F + kc * 32 + a_c16 * 8;
            cp16(s0 + ST_B_HI + so, g_Bhi + gsrc);
            cp16(s0 + ST_B_LO + so, g_Blo + gsrc);
        }
        cp_commit();
    };

    load_stage(0, 0);

    for (int kc = 0; kc < NCHUNK; kc++) {
        if (kc + 1 < NCHUNK) load_stage(kc + 1, (kc + 1) & 1);
        if (kc + 1 < NCHUNK) cp_wait<1>(); else cp_wait<0>();
        __syncthreads();

        const uint32_t s0 = sb + (kc & 1) * STAGE;
        const uint32_t a_hi_b = s0 + ST_A_HI + arow * 64;
        const uint32_t a_lo_b = s0 + ST_A_LO + arow * 64;
        const uint32_t b_hi_b = s0 + ST_B_HI + brow * 64;
        const uint32_t b_lo_b = s0 + ST_B_LO + brow * 64;
#pragma unroll
        for (int ks = 0; ks < 2; ks++) {
            const uint32_t akb = ((uint32_t)(ks * 32) + a_klane) ^ a_xor;
            const uint32_t bkb = ((uint32_t)(ks * 32) + b_klane) ^ b_xor;
            uint32_t af[2][4], bh[2][4], bl[2][4];
#pragma unroll
            for (int i = 0; i < 2; i++)
                ldsm4(af[i], a_hi_b + i * 1024 + akb);
#pragma unroll
            for (int jp = 0; jp < 2; jp++)
                ldsm4(bh[jp], b_hi_b + jp * 1024 + bkb);
#pragma unroll
            for (int i = 0; i < 2; i++)
#pragma unroll
                for (int j = 0; j < 4; j++)
                    mma_bf16(acc[i][j], af[i], &bh[j >> 1][(j & 1) * 2]);
#pragma unroll
            for (int jp = 0; jp < 2; jp++)
                ldsm4(bl[jp], b_lo_b + jp * 1024 + bkb);
#pragma unroll
            for (int i = 0; i < 2; i++)
#pragma unroll
                for (int j = 0; j < 4; j++)
                    mma_bf16(acc[i][j], af[i], &bl[j >> 1][(j & 1) * 2]);
#pragma unroll
            for (int i = 0; i < 2; i++)
                ldsm4(af[i], a_lo_b + i * 1024 + akb);
#pragma unroll
            for (int i = 0; i < 2; i++)
#pragma unroll
                for (int j = 0; j < 4; j++)
                    mma_bf16(acc[i][j], af[i], &bh[j >> 1][(j & 1) * 2]);
        }
        __syncthreads();
    }

    // ---- epilogue: bias + X store + fused s1/s2 partials --------------------
    float* s1b = reinterpret_cast<float*>(smem);          // [128]
    float* s2b = reinterpret_cast<float*>(smem) + 128;    // [128]
    if (tid < 128) { s1b[tid] = 0.f; s2b[tid] = 0.f; }
    __syncthreads();

    const int chbase = bn - h * 128;                      // 0 or 64
    const float* a1 = a_attn + h * 2 * HID + chbase;
    const float* a2 = a1 + HID;
#pragma unroll
    for (int i = 0; i < 2; i++) {
        int r0 = wm * 32 + i * 16 + (lane >> 2);
        float p1a = 0.f, p2a = 0.f, p1b = 0.f, p2b = 0.f;
#pragma unroll
        for (int j = 0; j < 4; j++) {
            int c = wn * 32 + j * 8 + 2 * (lane & 3);
            float b0 = bias[bn + c], b1 = bias[bn + c + 1];
            float x00 = acc[i][j][0] + b0, x01 = acc[i][j][1] + b1;
            float x10 = acc[i][j][2] + b0, x11 = acc[i][j][3] + b1;
            int gr0 = bm + r0, gr1 = gr0 + 8;
            if (gr0 < NN)
                *reinterpret_cast<float2*>(g_X + (size_t)gr0 * COLS + bn + c) =
                    make_float2(x00, x01);
            if (gr1 < NN)
                *reinterpret_cast<float2*>(g_X + (size_t)gr1 * COLS + bn + c) =
                    make_float2(x10, x11);
            float w10 = a1[c], w11 = a1[c + 1], w20 = a2[c], w21 = a2[c + 1];
            p1a = fmaf(x00, w10, fmaf(x01, w11, p1a));
            p2a = fmaf(x00, w20, fmaf(x01, w21, p2a));
            p1b = fmaf(x10, w10, fmaf(x11, w11, p1b));
            p2b = fmaf(x10, w20, fmaf(x11, w21, p2b));
        }
#pragma unroll
        for (int o = 1; o <= 2; o <<= 1) {
            p1a += __shfl_xor_sync(0xffffffffu, p1a, o);
            p2a += __shfl_xor_sync(0xffffffffu, p2a, o);
            p1b += __shfl_xor_sync(0xffffffffu, p1b, o);
            p2b += __shfl_xor_sync(0xffffffffu, p2b, o);
        }
        if ((lane & 3) == 0) {
            atomicAdd(&s1b[r0], p1a);
            atomicAdd(&s2b[r0], p2a);
            atomicAdd(&s1b[r0 + 8], p1b);
            atomicAdd(&s2b[r0 + 8], p2b);
        }
    }
    __syncthreads();
    if (tid < 128 && bm + tid < NN) {
        atomicAdd(&g_s1[(bm + tid) * 4 + h], s1b[tid]);
        atomicAdd(&g_s2[(bm + tid) * 4 + h], s2b[tid]);
    }
}

// ---------------- edge kernels ----------------------------------------------
__global__ void hist_kernel(const void* __restrict__ edge) {
    int e = blockIdx.x * blockDim.x + threadIdx.x;
    if (e >= EE) return;
    int src = load_edge(edge, e);
    atomicAdd(&g_deg[src], 1);
}

// 1024-thread two-level warp-shuffle scan over 50000 degrees.
__global__ __launch_bounds__(1024) void scan_kernel() {
    __shared__ int wsum[32];
    const int t    = threadIdx.x;
    const int lane = t & 31, wd = t >> 5;
    const int CH   = (NN + 1023) / 1024;       // 49
    int beg = t * CH, end = min(beg + CH, NN);
    int s = 0;
    for (int i = beg; i < end; i++) s += g_deg[i];
    // inclusive warp scan
    int v = s;
#pragma unroll
    for (int o = 1; o < 32; o <<= 1) {
        int u = __shfl_up_sync(0xffffffffu, v, o);
        if (lane >= o) v += u;
    }
    if (lane == 31) wsum[wd] = v;
    __syncthreads();
    if (wd == 0) {
        int w = wsum[lane];
#pragma unroll
        for (int o = 1; o < 32; o <<= 1) {
            int u = __shfl_up_sync(0xffffffffu, w, o);
            if (lane >= o) w += u;
        }
        wsum[lane] = w;
    }
    __syncthreads();
    int run = (v - s) + (wd ? wsum[wd - 1] : 0);   // exclusive prefix
    for (int i = beg; i < end; i++) {
        g_rowptr[i] = run;
        g_cursor[i] = run;
        run += g_deg[i];
    }
    if (t == 0) g_rowptr[NN] = EE;
}

__global__ __launch_bounds__(256) void score_scatter_kernel(const void* __restrict__ edge) {
    int e = blockIdx.x * blockDim.x + threadIdx.x;
    if (e >= EE) return;
    int src = load_edge(edge, e);
    int dst = load_edge(edge, (long long)EE + e);
    float4 v1 = *reinterpret_cast<const float4*>(g_s1 + src * 4);
    float4 v2 = *reinterpret_cast<const float4*>(g_s2 + dst * 4);
    float4 sc;
    {
        float s0 = v1.x + v2.x, s1 = v1.y + v2.y, s2 = v1.z + v2.z, s3 = v1.w + v2.w;
        s0 = (s0 >= 0.f ? s0 : ALPHA_L * s0) * INV_SCALE;
        s1 = (s1 >= 0.f ? s1 : ALPHA_L * s1) * INV_SCALE;
        s2 = (s2 >= 0.f ? s2 : ALPHA_L * s2) * INV_SCALE;
        s3 = (s3 >= 0.f ? s3 : ALPHA_L * s3) * INV_SCALE;
        sc = make_float4(__expf(s0), __expf(s1), __expf(s2), __expf(s3));
    }
    int pos = atomicAdd(&g_cursor[src], 1);
    g_dsts[pos] = dst;
    g_es[pos]   = sc;
}

// One block (128 thr) per node: gather-aggregate + LayerNorm + ELU.
__global__ __launch_bounds__(128) void agg_ln_kernel(
    const float* __restrict__ gain, const float* __restrict__ beta,
    float* __restrict__ out)
{
    const int n = blockIdx.x;
    const int t = threadIdx.x;
    const int beg = g_rowptr[n], end = g_rowptr[n + 1];

    float a0 = 0.f, a1 = 0.f, a2 = 0.f, a3 = 0.f;
    float r0 = 0.f, r1 = 0.f, r2 = 0.f, r3 = 0.f;
    int d = 0; float4 e = make_float4(0.f, 0.f, 0.f, 0.f);
    if (beg < end) { d = __ldcs(&g_dsts[beg]); e = __ldcs(&g_es[beg]); }
    for (int i = beg; i < end; i++) {
        int dn = 0; float4 en;
        if (i + 1 < end) { dn = __ldcs(&g_dsts[i + 1]); en = __ldcs(&g_es[i + 1]); }
        else             { en = make_float4(0.f, 0.f, 0.f, 0.f); }
        const float* xr = g_X + (size_t)d * COLS;
        a0 = fmaf(e.x, xr[t],            a0);
        a1 = fmaf(e.y, xr[HID + t],      a1);
        a2 = fmaf(e.z, xr[2 * HID + t],  a2);
        a3 = fmaf(e.w, xr[3 * HID + t],  a3);
        r0 += e.x; r1 += e.y; r2 += e.z; r3 += e.w;
        d = dn; e = en;
    }
    float h0 = a0 / (r0 == 0.f ? 1.f : r0);
    float h1 = a1 / (r1 == 0.f ? 1.f : r1);
    float h2 = a2 / (r2 == 0.f ? 1.f : r2);
    float h3 = a3 / (r3 == 0.f ? 1.f : r3);

    float s  = h0 + h1 + h2 + h3;
    float ss = h0 * h0 + h1 * h1 + h2 * h2 + h3 * h3;
#pragma unroll
    for (int o = 16; o; o >>= 1) {
        s  += __shfl_xor_sync(0xffffffffu, s, o);
        ss += __shfl_xor_sync(0xffffffffu, ss, o);
    }
    __shared__ float rs[4], rss[4];
    int w = t >> 5;
    if ((t & 31) == 0) { rs[w] = s; rss[w] = ss; }
    __syncthreads();
    s  = rs[0] + rs[1] + rs[2] + rs[3];
    ss = rss[0] + rss[1] + rss[2] + rss[3];

    float mean = s * (1.f / 512.f);
    float var  = fmaxf((ss - 512.f * mean * mean) * (1.f / 511.f), 0.f);
    float inv  = 1.f / (sqrtf(var) + LN_EPS);

    float* orow = out + (size_t)n * COLS;
    float hv[4] = {h0, h1, h2, h3};
#pragma unroll
    for (int h = 0; h < 4; h++) {
        int c = h * HID + t;
        float v = gain[c] * (hv[h] - mean) * inv + beta[c];
        orow[c] = v > 0.f ? v : expm1f(v);
    }
}

// ---------------- launch -----------------------------------------------------
extern "C" void kernel_launch(void* const* d_in, const int* in_sizes, int n_in,
                              void* d_out, int out_size)
{
    (void)in_sizes; (void)n_in; (void)out_size;
    const void*  edge   = d_in[1];
    const float* emb    = (const float*)d_in[2];
    const float* W      = (const float*)d_in[3];
    const float* bias   = (const float*)d_in[4];
    const float* a_attn = (const float*)d_in[5];
    const float* gain   = (const float*)d_in[6];
    const float* beta   = (const float*)d_in[7];
    float* out = (float*)d_out;

    prep_kernel<<<PREP_A_BLOCKS, 256>>>(emb, W, (const int*)edge);

    dim3 gg(M_TILES, 8);
    gemm_mma_kernel<<<gg, 256>>>(bias, a_attn);

    hist_kernel<<<(EE + 255) / 256, 256>>>(edge);
    scan_kernel<<<1, 1024>>>();
    score_scatter_kernel<<<(EE + 255) / 256, 256>>>(edge);

    agg_ln_kernel<<<NN, 128>>>(gain, beta, out);
}

// round 9
// speedup vs baseline: 1.2067x; 1.2067x over previous
#include <cuda_runtime.h>
#include <cuda_bf16.h>
#include <math.h>
#include <stdint.h>

#define NN      50000
#define IN_F    256
#define HID     128
#define HEADS   4
#define EE      800000
#define COLS    (HEADS * HID)          // 512
#define ALPHA_L 0.2f
#define INV_SCALE 0.04419417382415922f // 1/sqrt(512)
#define LN_EPS  1e-6f

#define M_TILES ((NN + 127) / 128)     // 391
#define M_PAD   (M_TILES * 128)        // 50048

#define PREP_A_BLOCKS (M_PAD * (IN_F / 4) / 256)   // 12512 exactly
#define ZERO_BLOCKS   ((NN * HEADS + 255) / 256)   // 782
#define PREPB_BLOCKS  ((COLS * IN_F) / 256)        // 512
#define OFF_BLOCKS    ((NN + 255) / 256)           // 196

// ---------------- scratch (static device memory; no allocations) ------------
__device__ float          g_X[(size_t)NN * COLS];     // 102.4 MB
__device__ float          g_s1[NN * HEADS];
__device__ float          g_s2[NN * HEADS];
__device__ __nv_bfloat16  g_Ahi[(size_t)M_PAD * IN_F];
__device__ __nv_bfloat16  g_Alo[(size_t)M_PAD * IN_F];
__device__ __nv_bfloat16  g_Bhi[COLS * IN_F];         // W split hi (512x256)
__device__ __nv_bfloat16  g_Blo[COLS * IN_F];
__device__ float4         g_es[EE];
__device__ int            g_dsts[EE];
__device__ int            g_deg[NN];
__device__ int            g_rowbeg[NN];
__device__ int            g_cursor[NN];
__device__ int            g_alloc;
__device__ int            g_is64;

// ---------------- helpers ---------------------------------------------------
__device__ __forceinline__ int load_edge(const void* e, long long idx) {
    if (g_is64) return (int)((const long long*)e)[idx];
    return ((const int*)e)[idx];
}
__device__ __forceinline__ uint32_t smem_u32(const void* p) {
    uint32_t a;
    asm("{ .reg .u64 t; cvta.to.shared.u64 t, %1; cvt.u32.u64 %0, t; }"
        : "=r"(a) : "l"(p));
    return a;
}
__device__ __forceinline__ void ldsm4(uint32_t* r, uint32_t addr) {
    asm volatile("ldmatrix.sync.aligned.m8n8.x4.shared.b16 {%0,%1,%2,%3}, [%4];"
                 : "=r"(r[0]), "=r"(r[1]), "=r"(r[2]), "=r"(r[3]) : "r"(addr));
}
__device__ __forceinline__ void mma_bf16(float* c, const uint32_t* a,
                                         const uint32_t* b) {
    asm volatile(
        "mma.sync.aligned.m16n8k16.row.col.f32.bf16.bf16.f32 "
        "{%0,%1,%2,%3}, {%4,%5,%6,%7}, {%8,%9}, {%0,%1,%2,%3};"
        : "+f"(c[0]), "+f"(c[1]), "+f"(c[2]), "+f"(c[3])
        : "r"(a[0]), "r"(a[1]), "r"(a[2]), "r"(a[3]), "r"(b[0]), "r"(b[1]));
}
__device__ __forceinline__ void cp16(uint32_t saddr, const void* gptr) {
    asm volatile("cp.async.cg.shared.global [%0], [%1], 16;"
                 :: "r"(saddr), "l"(gptr));
}
__device__ __forceinline__ void cp_commit() {
    asm volatile("cp.async.commit_group;" ::: "memory");
}
template <int N>
__device__ __forceinline__ void cp_wait() {
    asm volatile("cp.async.wait_group %0;" :: "n"(N) : "memory");
}
// SW64 swizzle for 64B rows: chunk16 index ^= (row>>1)&3
__device__ __forceinline__ uint32_t swz64(uint32_t row, uint32_t cbyte) {
    return row * 64 + (cbyte ^ (((row >> 1) & 3) << 4));
}
__device__ __forceinline__ uint32_t pack2(__nv_bfloat16 a, __nv_bfloat16 b) {
    return (uint32_t)__bfloat16_as_ushort(a) | ((uint32_t)__bfloat16_as_ushort(b) << 16);
}

// gemm smem: 2 stages x 24KB (A hi 8K, A lo 8K, B hi 4K, B lo 4K) = 48KB static
#define ST_A_HI 0
#define ST_A_LO 8192
#define ST_B_HI 16384
#define ST_B_LO 20480
#define STAGE   24576
#define NCHUNK  8                      // 256 / 32

// ---------------- merged prep kernel -----------------------------------------
__global__ void prep_kernel(const float* __restrict__ emb,
                            const float* __restrict__ W,
                            const int*   __restrict__ edge_raw)
{
    const int b   = blockIdx.x;
    const int tid = threadIdx.x;

    // ---- detect (block 0, warp 0) + alloc counter reset ----
    if (b == 0 && tid < 32) {
        int bad = 0;
        for (int i = tid; i < 2048; i += 32)
            if (edge_raw[2 * i + 1] != 0) bad = 1;
        unsigned m = __ballot_sync(0xffffffffu, bad);
        if (tid == 0) g_is64 = (m == 0);
    }
    if (b == 0 && tid == 32) g_alloc = 0;
    // ---- zero s1/s2/deg ----
    if (b < ZERO_BLOCKS) {
        int i = b * 256 + tid;
        if (i < NN * HEADS) { g_s1[i] = 0.f; g_s2[i] = 0.f; }
        if (i < NN) g_deg[i] = 0;
    }
    // ---- W split ----
    if (b < PREPB_BLOCKS) {
        int i = b * 256 + tid;
        float w = W[i];
        __nv_bfloat16 hi = __float2bfloat16(w);
        __nv_bfloat16 lo = __float2bfloat16(w - __bfloat162float(hi));
        g_Bhi[i] = hi;
        g_Blo[i] = lo;
    }
    // ---- emb split (every block) ----
    {
        int i = b * 256 + tid;                      // float4 granularity
        int row = i >> 6;
        int c4  = i & 63;
        float4 v = make_float4(0.f, 0.f, 0.f, 0.f);
        if (row < NN && row != 0)
            v = *reinterpret_cast<const float4*>(emb + (size_t)row * IN_F + c4 * 4);
        __nv_bfloat16 h0 = __float2bfloat16(v.x), h1 = __float2bfloat16(v.y);
        __nv_bfloat16 h2 = __float2bfloat16(v.z), h3 = __float2bfloat16(v.w);
        __nv_bfloat16 l0 = __float2bfloat16(v.x - __bfloat162float(h0));
        __nv_bfloat16 l1 = __float2bfloat16(v.y - __bfloat162float(h1));
        __nv_bfloat16 l2 = __float2bfloat16(v.z - __bfloat162float(h2));
        __nv_bfloat16 l3 = __float2bfloat16(v.w - __bfloat162float(h3));
        size_t off = (size_t)row * IN_F + c4 * 4;
        *reinterpret_cast<uint2*>(g_Ahi + off) = make_uint2(pack2(h0, h1), pack2(h2, h3));
        *reinterpret_cast<uint2*>(g_Alo + off) = make_uint2(pack2(l0, l1), pack2(l2, l3));
    }
}

// ---------------- split-bf16 HMMA GEMM, cp.async double-buffered -------------
__global__ __launch_bounds__(256, 2) void gemm_mma_kernel(
    const float* __restrict__ bias, const float* __restrict__ a_attn)
{
    __shared__ char smem[2 * STAGE];
    const uint32_t sb = smem_u32(smem);
    const int tid  = threadIdx.x;
    const int wid  = tid >> 5;
    const int lane = tid & 31;
    const int wm   = wid & 3;        // 0..3 (rows)
    const int wn   = wid >> 2;       // 0..1 (cols)
    const int bm   = blockIdx.x * 128;
    const int bn   = blockIdx.y * 64;
    const int h    = bn >> 7;        // head

    float acc[2][4][4];
#pragma unroll
    for (int i = 0; i < 2; i++)
#pragma unroll
        for (int j = 0; j < 4; j++)
#pragma unroll
            for (int r = 0; r < 4; r++) acc[i][j][r] = 0.f;

    const int a_row0 = tid >> 2;
    const int a_c16  = tid & 3;
    const int b_row  = tid >> 2;
    const int arow = wm * 32 + (lane & 15);
    const uint32_t a_klane = (uint32_t)((lane >> 4) << 4);
    const uint32_t a_xor   = (uint32_t)(((arow >> 1) & 3) << 4);
    const int m4   = lane >> 3;
    const int brow = wn * 32 + ((m4 >> 1) << 3) + (lane & 7);
    const uint32_t b_klane = (uint32_t)((m4 & 1) << 4);
    const uint32_t b_xor   = (uint32_t)(((brow >> 1) & 3) << 4);

    auto load_stage = [&](int kc, int buf) {
        uint32_t s0 = sb + buf * STAGE;
#pragma unroll
        for (int l = 0; l < 2; l++) {
            int row = a_row0 + 64 * l;
            uint32_t so = swz64(row, a_c16 * 16);
            size_t gsrc = (size_t)(bm + row) * IN_F + kc * 32 + a_c16 * 8;
            cp16(s0 + ST_A_HI + so, g_Ahi + gsrc);
            cp16(s0 + ST_A_LO + so, g_Alo + gsrc);
        }
        {
            uint32_t so = swz64(b_row, a_c16 * 16);
            size_t gsrc = (size_t)(bn + b_row) * IN_F + kc * 32 + a_c16 * 8;
            cp16(s0 + ST_B_HI + so, g_Bhi + gsrc);
            cp16(s0 + ST_B_LO + so, g_Blo + gsrc);
        }
        cp_commit();
    };

    load_stage(0, 0);

    for (int kc = 0; kc < NCHUNK; kc++) {
        if (kc + 1 < NCHUNK) load_stage(kc + 1, (kc + 1) & 1);
        if (kc + 1 < NCHUNK) cp_wait<1>(); else cp_wait<0>();
        __syncthreads();

        const uint32_t s0 = sb + (kc & 1) * STAGE;
        const uint32_t a_hi_b = s0 + ST_A_HI + arow * 64;
        const uint32_t a_lo_b = s0 + ST_A_LO + arow * 64;
        const uint32_t b_hi_b = s0 + ST_B_HI + brow * 64;
        const uint32_t b_lo_b = s0 + ST_B_LO + brow * 64;
#pragma unroll
        for (int ks = 0; ks < 2; ks++) {
            const uint32_t akb = ((uint32_t)(ks * 32) + a_klane) ^ a_xor;
            const uint32_t bkb = ((uint32_t)(ks * 32) + b_klane) ^ b_xor;
            uint32_t af[2][4], bh[2][4], bl[2][4];
#pragma unroll
            for (int i = 0; i < 2; i++)
                ldsm4(af[i], a_hi_b + i * 1024 + akb);
#pragma unroll
            for (int jp = 0; jp < 2; jp++)
                ldsm4(bh[jp], b_hi_b + jp * 1024 + bkb);
#pragma unroll
            for (int i = 0; i < 2; i++)
#pragma unroll
                for (int j = 0; j < 4; j++)
                    mma_bf16(acc[i][j], af[i], &bh[j >> 1][(j & 1) * 2]);
#pragma unroll
            for (int jp = 0; jp < 2; jp++)
                ldsm4(bl[jp], b_lo_b + jp * 1024 + bkb);
#pragma unroll
            for (int i = 0; i < 2; i++)
#pragma unroll
                for (int j = 0; j < 4; j++)
                    mma_bf16(acc[i][j], af[i], &bl[j >> 1][(j & 1) * 2]);
#pragma unroll
            for (int i = 0; i < 2; i++)
                ldsm4(af[i], a_lo_b + i * 1024 + akb);
#pragma unroll
            for (int i = 0; i < 2; i++)
#pragma unroll
                for (int j = 0; j < 4; j++)
                    mma_bf16(acc[i][j], af[i], &bh[j >> 1][(j & 1) * 2]);
        }
        __syncthreads();
    }

    // ---- epilogue: bias + X store + fused s1/s2 partials --------------------
    float* s1b = reinterpret_cast<float*>(smem);          // [128]
    float* s2b = reinterpret_cast<float*>(smem) + 128;    // [128]
    if (tid < 128) { s1b[tid] = 0.f; s2b[tid] = 0.f; }
    __syncthreads();

    const int chbase = bn - h * 128;                      // 0 or 64
    const float* a1 = a_attn + h * 2 * HID + chbase;
    const float* a2 = a1 + HID;
#pragma unroll
    for (int i = 0; i < 2; i++) {
        int r0 = wm * 32 + i * 16 + (lane >> 2);
        float p1a = 0.f, p2a = 0.f, p1b = 0.f, p2b = 0.f;
#pragma unroll
        for (int j = 0; j < 4; j++) {
            int c = wn * 32 + j * 8 + 2 * (lane & 3);
            float b0 = bias[bn + c], b1 = bias[bn + c + 1];
            float x00 = acc[i][j][0] + b0, x01 = acc[i][j][1] + b1;
            float x10 = acc[i][j][2] + b0, x11 = acc[i][j][3] + b1;
            int gr0 = bm + r0, gr1 = gr0 + 8;
            if (gr0 < NN)
                *reinterpret_cast<float2*>(g_X + (size_t)gr0 * COLS + bn + c) =
                    make_float2(x00, x01);
            if (gr1 < NN)
                *reinterpret_cast<float2*>(g_X + (size_t)gr1 * COLS + bn + c) =
                    make_float2(x10, x11);
            float w10 = a1[c], w11 = a1[c + 1], w20 = a2[c], w21 = a2[c + 1];
            p1a = fmaf(x00, w10, fmaf(x01, w11, p1a));
            p2a = fmaf(x00, w20, fmaf(x01, w21, p2a));
            p1b = fmaf(x10, w10, fmaf(x11, w11, p1b));
            p2b = fmaf(x10, w20, fmaf(x11, w21, p2b));
        }
#pragma unroll
        for (int o = 1; o <= 2; o <<= 1) {
            p1a += __shfl_xor_sync(0xffffffffu, p1a, o);
            p2a += __shfl_xor_sync(0xffffffffu, p2a, o);
            p1b += __shfl_xor_sync(0xffffffffu, p1b, o);
            p2b += __shfl_xor_sync(0xffffffffu, p2b, o);
        }
        if ((lane & 3) == 0) {
            atomicAdd(&s1b[r0], p1a);
            atomicAdd(&s2b[r0], p2a);
            atomicAdd(&s1b[r0 + 8], p1b);
            atomicAdd(&s2b[r0 + 8], p2b);
        }
    }
    __syncthreads();
    if (tid < 128 && bm + tid < NN) {
        atomicAdd(&g_s1[(bm + tid) * 4 + h], s1b[tid]);
        atomicAdd(&g_s2[(bm + tid) * 4 + h], s2b[tid]);
    }
}

// ---------------- edge kernels ----------------------------------------------
__global__ void hist_kernel(const void* __restrict__ edge) {
    int e = blockIdx.x * blockDim.x + threadIdx.x;
    if (e >= EE) return;
    int src = load_edge(edge, e);
    atomicAdd(&g_deg[src], 1);
}

// 196-block atomic-offset allocator. Each block scans 256 degrees with warp
// shuffles, leader grabs a global base with ONE atomicAdd. Segment placement
// is allocation-order dependent, but each node's segment is contiguous and
// its edge membership identical -> output invariant (within fp tolerance).
__global__ __launch_bounds__(256) void offset_kernel() {
    __shared__ int wsum[8];
    __shared__ int sbase;
    const int tid = threadIdx.x, lane = tid & 31, wd = tid >> 5;
    const int n = blockIdx.x * 256 + tid;
    int d = (n < NN) ? g_deg[n] : 0;
    int v = d;
#pragma unroll
    for (int o = 1; o < 32; o <<= 1) {
        int u = __shfl_up_sync(0xffffffffu, v, o);
        if (lane >= o) v += u;
    }
    if (lane == 31) wsum[wd] = v;
    __syncthreads();
    if (tid == 0) {
        int run = 0;
#pragma unroll
        for (int i = 0; i < 8; i++) { int t = wsum[i]; wsum[i] = run; run += t; }
        sbase = atomicAdd(&g_alloc, run);
    }
    __syncthreads();
    int beg = sbase + wsum[wd] + v - d;   // exclusive prefix + block base
    if (n < NN) { g_rowbeg[n] = beg; g_cursor[n] = beg; }
}

__global__ __launch_bounds__(256) void score_scatter_kernel(const void* __restrict__ edge) {
    int e = blockIdx.x * blockDim.x + threadIdx.x;
    if (e >= EE) return;
    int src = load_edge(edge, e);
    int dst = load_edge(edge, (long long)EE + e);
    float4 v1 = *reinterpret_cast<const float4*>(g_s1 + src * 4);
    float4 v2 = *reinterpret_cast<const float4*>(g_s2 + dst * 4);
    float4 sc;
    {
        float s0 = v1.x + v2.x, s1 = v1.y + v2.y, s2 = v1.z + v2.z, s3 = v1.w + v2.w;
        s0 = (s0 >= 0.f ? s0 : ALPHA_L * s0) * INV_SCALE;
        s1 = (s1 >= 0.f ? s1 : ALPHA_L * s1) * INV_SCALE;
        s2 = (s2 >= 0.f ? s2 : ALPHA_L * s2) * INV_SCALE;
        s3 = (s3 >= 0.f ? s3 : ALPHA_L * s3) * INV_SCALE;
        sc = make_float4(__expf(s0), __expf(s1), __expf(s2), __expf(s3));
    }
    int pos = atomicAdd(&g_cursor[src], 1);
    g_dsts[pos] = dst;
    g_es[pos]   = sc;
}

// One block (128 thr) per node: gather-aggregate + LayerNorm + ELU.
__global__ __launch_bounds__(128) void agg_ln_kernel(
    const float* __restrict__ gain, const float* __restrict__ beta,
    float* __restrict__ out)
{
    const int n = blockIdx.x;
    const int t = threadIdx.x;
    const int beg = g_rowbeg[n], end = beg + g_deg[n];

    float a0 = 0.f, a1 = 0.f, a2 = 0.f, a3 = 0.f;
    float r0 = 0.f, r1 = 0.f, r2 = 0.f, r3 = 0.f;
    int d = 0; float4 e = make_float4(0.f, 0.f, 0.f, 0.f);
    if (beg < end) { d = __ldcs(&g_dsts[beg]); e = __ldcs(&g_es[beg]); }
    for (int i = beg; i < end; i++) {
        int dn = 0; float4 en;
        if (i + 1 < end) { dn = __ldcs(&g_dsts[i + 1]); en = __ldcs(&g_es[i + 1]); }
        else             { en = make_float4(0.f, 0.f, 0.f, 0.f); }
        const float* xr = g_X + (size_t)d * COLS;
        a0 = fmaf(e.x, xr[t],            a0);
        a1 = fmaf(e.y, xr[HID + t],      a1);
        a2 = fmaf(e.z, xr[2 * HID + t],  a2);
        a3 = fmaf(e.w, xr[3 * HID + t],  a3);
        r0 += e.x; r1 += e.y; r2 += e.z; r3 += e.w;
        d = dn; e = en;
    }
    float h0 = a0 / (r0 == 0.f ? 1.f : r0);
    float h1 = a1 / (r1 == 0.f ? 1.f : r1);
    float h2 = a2 / (r2 == 0.f ? 1.f : r2);
    float h3 = a3 / (r3 == 0.f ? 1.f : r3);

    float s  = h0 + h1 + h2 + h3;
    float ss = h0 * h0 + h1 * h1 + h2 * h2 + h3 * h3;
#pragma unroll
    for (int o = 16; o; o >>= 1) {
        s  += __shfl_xor_sync(0xffffffffu, s, o);
        ss += __shfl_xor_sync(0xffffffffu, ss, o);
    }
    __shared__ float rs[4], rss[4];
    int w = t >> 5;
    if ((t & 31) == 0) { rs[w] = s; rss[w] = ss; }
    __syncthreads();
    s  = rs[0] + rs[1] + rs[2] + rs[3];
    ss = rss[0] + rss[1] + rss[2] + rss[3];

    float mean = s * (1.f / 512.f);
    float var  = fmaxf((ss - 512.f * mean * mean) * (1.f / 511.f), 0.f);
    float inv  = 1.f / (sqrtf(var) + LN_EPS);

    float* orow = out + (size_t)n * COLS;
    float hv[4] = {h0, h1, h2, h3};
#pragma unroll
    for (int h = 0; h < 4; h++) {
        int c = h * HID + t;
        float v = gain[c] * (hv[h] - mean) * inv + beta[c];
        orow[c] = v > 0.f ? v : expm1f(v);
    }
}

// ---------------- launch -----------------------------------------------------
extern "C" void kernel_launch(void* const* d_in, const int* in_sizes, int n_in,
                              void* d_out, int out_size)
{
    (void)in_sizes; (void)n_in; (void)out_size;
    const void*  edge   = d_in[1];
    const float* emb    = (const float*)d_in[2];
    const float* W      = (const float*)d_in[3];
    const float* bias   = (const float*)d_in[4];
    const float* a_attn = (const float*)d_in[5];
    const float* gain   = (const float*)d_in[6];
    const float* beta   = (const float*)d_in[7];
    float* out = (float*)d_out;

    prep_kernel<<<PREP_A_BLOCKS, 256>>>(emb, W, (const int*)edge);

    dim3 gg(M_TILES, 8);
    gemm_mma_kernel<<<gg, 256>>>(bias, a_attn);

    hist_kernel<<<(EE + 255) / 256, 256>>>(edge);
    offset_kernel<<<OFF_BLOCKS, 256>>>();
    score_scatter_kernel<<<(EE + 255) / 256, 256>>>(edge);

    agg_ln_kernel<<<NN, 128>>>(gain, beta, out);
}

// round 10
// speedup vs baseline: 1.3376x; 1.1085x over previous
#include <cuda_runtime.h>
#include <cuda_bf16.h>
#include <cuda_fp16.h>
#include <math.h>
#include <stdint.h>

#define NN      50000
#define IN_F    256
#define HID     128
#define HEADS   4
#define EE      800000
#define COLS    (HEADS * HID)          // 512
#define ALPHA_L 0.2f
#define INV_SCALE 0.04419417382415922f // 1/sqrt(512)
#define LN_EPS  1e-6f

#define M_TILES ((NN + 127) / 128)     // 391
#define M_PAD   (M_TILES * 128)        // 50048

#define PREP_A_BLOCKS (M_PAD * (IN_F / 4) / 256)   // 12512 exactly
#define ZERO_BLOCKS   ((NN * HEADS + 255) / 256)   // 782
#define PREPB_BLOCKS  ((COLS * IN_F) / 256)        // 512
#define OFF_BLOCKS    ((NN + 255) / 256)           // 196

// ---------------- scratch (static device memory; no allocations) ------------
__device__ __half         g_Xh[(size_t)NN * COLS];    // 51.2 MB (L2-resident)
__device__ float          g_s1[NN * HEADS];
__device__ float          g_s2[NN * HEADS];
__device__ __nv_bfloat16  g_Ahi[(size_t)M_PAD * IN_F];
__device__ __nv_bfloat16  g_Alo[(size_t)M_PAD * IN_F];
__device__ __nv_bfloat16  g_Bhi[COLS * IN_F];         // W split hi (512x256)
__device__ __nv_bfloat16  g_Blo[COLS * IN_F];
__device__ float4         g_es[EE];
__device__ int            g_dsts[EE];
__device__ int            g_deg[NN];
__device__ int            g_rowbeg[NN];
__device__ int            g_cursor[NN];
__device__ int            g_alloc;
__device__ int            g_is64;

// ---------------- helpers ---------------------------------------------------
__device__ __forceinline__ int load_edge(const void* e, long long idx) {
    if (g_is64) return (int)((const long long*)e)[idx];
    return ((const int*)e)[idx];
}
__device__ __forceinline__ uint32_t smem_u32(const void* p) {
    uint32_t a;
    asm("{ .reg .u64 t; cvta.to.shared.u64 t, %1; cvt.u32.u64 %0, t; }"
        : "=r"(a) : "l"(p));
    return a;
}
__device__ __forceinline__ void ldsm4(uint32_t* r, uint32_t addr) {
    asm volatile("ldmatrix.sync.aligned.m8n8.x4.shared.b16 {%0,%1,%2,%3}, [%4];"
                 : "=r"(r[0]), "=r"(r[1]), "=r"(r[2]), "=r"(r[3]) : "r"(addr));
}
__device__ __forceinline__ void mma_bf16(float* c, const uint32_t* a,
                                         const uint32_t* b) {
    asm volatile(
        "mma.sync.aligned.m16n8k16.row.col.f32.bf16.bf16.f32 "
        "{%0,%1,%2,%3}, {%4,%5,%6,%7}, {%8,%9}, {%0,%1,%2,%3};"
        : "+f"(c[0]), "+f"(c[1]), "+f"(c[2]), "+f"(c[3])
        : "r"(a[0]), "r"(a[1]), "r"(a[2]), "r"(a[3]), "r"(b[0]), "r"(b[1]));
}
__device__ __forceinline__ void cp16(uint32_t saddr, const void* gptr) {
    asm volatile("cp.async.cg.shared.global [%0], [%1], 16;"
                 :: "r"(saddr), "l"(gptr));
}
__device__ __forceinline__ void cp_commit() {
    asm volatile("cp.async.commit_group;" ::: "memory");
}
template <int N>
__device__ __forceinline__ void cp_wait() {
    asm volatile("cp.async.wait_group %0;" :: "n"(N) : "memory");
}
// SW64 swizzle for 64B rows: chunk16 index ^= (row>>1)&3
__device__ __forceinline__ uint32_t swz64(uint32_t row, uint32_t cbyte) {
    return row * 64 + (cbyte ^ (((row >> 1) & 3) << 4));
}
__device__ __forceinline__ uint32_t pack2(__nv_bfloat16 a, __nv_bfloat16 b) {
    return (uint32_t)__bfloat16_as_ushort(a) | ((uint32_t)__bfloat16_as_ushort(b) << 16);
}

// gemm smem: 2 stages x 24KB (A hi 8K, A lo 8K, B hi 4K, B lo 4K) = 48KB static
#define ST_A_HI 0
#define ST_A_LO 8192
#define ST_B_HI 16384
#define ST_B_LO 20480
#define STAGE   24576
#define NCHUNK  8                      // 256 / 32

// ---------------- merged prep kernel -----------------------------------------
__global__ void prep_kernel(const float* __restrict__ emb,
                            const float* __restrict__ W,
                            const int*   __restrict__ edge_raw)
{
    const int b   = blockIdx.x;
    const int tid = threadIdx.x;

    // ---- detect (block 0, warp 0) + alloc counter reset ----
    if (b == 0 && tid < 32) {
        int bad = 0;
        for (int i = tid; i < 2048; i += 32)
            if (edge_raw[2 * i + 1] != 0) bad = 1;
        unsigned m = __ballot_sync(0xffffffffu, bad);
        if (tid == 0) g_is64 = (m == 0);
    }
    if (b == 0 && tid == 32) g_alloc = 0;
    // ---- zero s1/s2/deg ----
    if (b < ZERO_BLOCKS) {
        int i = b * 256 + tid;
        if (i < NN * HEADS) { g_s1[i] = 0.f; g_s2[i] = 0.f; }
        if (i < NN) g_deg[i] = 0;
    }
    // ---- W split ----
    if (b < PREPB_BLOCKS) {
        int i = b * 256 + tid;
        float w = W[i];
        __nv_bfloat16 hi = __float2bfloat16(w);
        __nv_bfloat16 lo = __float2bfloat16(w - __bfloat162float(hi));
        g_Bhi[i] = hi;
        g_Blo[i] = lo;
    }
    // ---- emb split (every block) ----
    {
        int i = b * 256 + tid;                      // float4 granularity
        int row = i >> 6;
        int c4  = i & 63;
        float4 v = make_float4(0.f, 0.f, 0.f, 0.f);
        if (row < NN && row != 0)
            v = *reinterpret_cast<const float4*>(emb + (size_t)row * IN_F + c4 * 4);
        __nv_bfloat16 h0 = __float2bfloat16(v.x), h1 = __float2bfloat16(v.y);
        __nv_bfloat16 h2 = __float2bfloat16(v.z), h3 = __float2bfloat16(v.w);
        __nv_bfloat16 l0 = __float2bfloat16(v.x - __bfloat162float(h0));
        __nv_bfloat16 l1 = __float2bfloat16(v.y - __bfloat162float(h1));
        __nv_bfloat16 l2 = __float2bfloat16(v.z - __bfloat162float(h2));
        __nv_bfloat16 l3 = __float2bfloat16(v.w - __bfloat162float(h3));
        size_t off = (size_t)row * IN_F + c4 * 4;
        *reinterpret_cast<uint2*>(g_Ahi + off) = make_uint2(pack2(h0, h1), pack2(h2, h3));
        *reinterpret_cast<uint2*>(g_Alo + off) = make_uint2(pack2(l0, l1), pack2(l2, l3));
    }
}

// ---------------- split-bf16 HMMA GEMM, cp.async double-buffered -------------
__global__ __launch_bounds__(256, 2) void gemm_mma_kernel(
    const float* __restrict__ bias, const float* __restrict__ a_attn)
{
    __shared__ char smem[2 * STAGE];
    const uint32_t sb = smem_u32(smem);
    const int tid  = threadIdx.x;
    const int wid  = tid >> 5;
    const int lane = tid & 31;
    const int wm   = wid & 3;        // 0..3 (rows)
    const int wn   = wid >> 2;       // 0..1 (cols)
    const int bm   = blockIdx.x * 128;
    const int bn   = blockIdx.y * 64;
    const int h    = bn >> 7;        // head

    float acc[2][4][4];
#pragma unroll
    for (int i = 0; i < 2; i++)
#pragma unroll
        for (int j = 0; j < 4; j++)
#pragma unroll
            for (int r = 0; r < 4; r++) acc[i][j][r] = 0.f;

    const int a_row0 = tid >> 2;
    const int a_c16  = tid & 3;
    const int b_row  = tid >> 2;
    const int arow = wm * 32 + (lane & 15);
    const uint32_t a_klane = (uint32_t)((lane >> 4) << 4);
    const uint32_t a_xor   = (uint32_t)(((arow >> 1) & 3) << 4);
    const int m4   = lane >> 3;
    const int brow = wn * 32 + ((m4 >> 1) << 3) + (lane & 7);
    const uint32_t b_klane = (uint32_t)((m4 & 1) << 4);
    const uint32_t b_xor   = (uint32_t)(((brow >> 1) & 3) << 4);

    auto load_stage = [&](int kc, int buf) {
        uint32_t s0 = sb + buf * STAGE;
#pragma unroll
        for (int l = 0; l < 2; l++) {
            int row = a_row0 + 64 * l;
            uint32_t so = swz64(row, a_c16 * 16);
            size_t gsrc = (size_t)(bm + row) * IN_F + kc * 32 + a_c16 * 8;
            cp16(s0 + ST_A_HI + so, g_Ahi + gsrc);
            cp16(s0 + ST_A_LO + so, g_Alo + gsrc);
        }
        {
            uint32_t so = swz64(b_row, a_c16 * 16);
            size_t gsrc = (size_t)(bn + b_row) * IN_F + kc * 32 + a_c16 * 8;
            cp16(s0 + ST_B_HI + so, g_Bhi + gsrc);
            cp16(s0 + ST_B_LO + so, g_Blo + gsrc);
        }
        cp_commit();
    };

    load_stage(0, 0);

    for (int kc = 0; kc < NCHUNK; kc++) {
        if (kc + 1 < NCHUNK) load_stage(kc + 1, (kc + 1) & 1);
        if (kc + 1 < NCHUNK) cp_wait<1>(); else cp_wait<0>();
        __syncthreads();

        const uint32_t s0 = sb + (kc & 1) * STAGE;
        const uint32_t a_hi_b = s0 + ST_A_HI + arow * 64;
        const uint32_t a_lo_b = s0 + ST_A_LO + arow * 64;
        const uint32_t b_hi_b = s0 + ST_B_HI + brow * 64;
        const uint32_t b_lo_b = s0 + ST_B_LO + brow * 64;
#pragma unroll
        for (int ks = 0; ks < 2; ks++) {
            const uint32_t akb = ((uint32_t)(ks * 32) + a_klane) ^ a_xor;
            const uint32_t bkb = ((uint32_t)(ks * 32) + b_klane) ^ b_xor;
            uint32_t af[2][4], bh[2][4], bl[2][4];
#pragma unroll
            for (int i = 0; i < 2; i++)
                ldsm4(af[i], a_hi_b + i * 1024 + akb);
#pragma unroll
            for (int jp = 0; jp < 2; jp++)
                ldsm4(bh[jp], b_hi_b + jp * 1024 + bkb);
#pragma unroll
            for (int i = 0; i < 2; i++)
#pragma unroll
                for (int j = 0; j < 4; j++)
                    mma_bf16(acc[i][j], af[i], &bh[j >> 1][(j & 1) * 2]);
#pragma unroll
            for (int jp = 0; jp < 2; jp++)
                ldsm4(bl[jp], b_lo_b + jp * 1024 + bkb);
#pragma unroll
            for (int i = 0; i < 2; i++)
#pragma unroll
                for (int j = 0; j < 4; j++)
                    mma_bf16(acc[i][j], af[i], &bl[j >> 1][(j & 1) * 2]);
#pragma unroll
            for (int i = 0; i < 2; i++)
                ldsm4(af[i], a_lo_b + i * 1024 + akb);
#pragma unroll
            for (int i = 0; i < 2; i++)
#pragma unroll
                for (int j = 0; j < 4; j++)
                    mma_bf16(acc[i][j], af[i], &bh[j >> 1][(j & 1) * 2]);
        }
        __syncthreads();
    }

    // ---- epilogue: bias + fp16 X store + fused s1/s2 partials ---------------
    float* s1b = reinterpret_cast<float*>(smem);          // [128]
    float* s2b = reinterpret_cast<float*>(smem) + 128;    // [128]
    if (tid < 128) { s1b[tid] = 0.f; s2b[tid] = 0.f; }
    __syncthreads();

    const int chbase = bn - h * 128;                      // 0 or 64
    const float* a1 = a_attn + h * 2 * HID + chbase;
    const float* a2 = a1 + HID;
#pragma unroll
    for (int i = 0; i < 2; i++) {
        int r0 = wm * 32 + i * 16 + (lane >> 2);
        float p1a = 0.f, p2a = 0.f, p1b = 0.f, p2b = 0.f;
#pragma unroll
        for (int j = 0; j < 4; j++) {
            int c = wn * 32 + j * 8 + 2 * (lane & 3);
            float b0 = bias[bn + c], b1 = bias[bn + c + 1];
            float x00 = acc[i][j][0] + b0, x01 = acc[i][j][1] + b1;
            float x10 = acc[i][j][2] + b0, x11 = acc[i][j][3] + b1;
            int gr0 = bm + r0, gr1 = gr0 + 8;
            if (gr0 < NN)
                *reinterpret_cast<__half2*>(g_Xh + (size_t)gr0 * COLS + bn + c) =
                    __floats2half2_rn(x00, x01);
            if (gr1 < NN)
                *reinterpret_cast<__half2*>(g_Xh + (size_t)gr1 * COLS + bn + c) =
                    __floats2half2_rn(x10, x11);
            float w10 = a1[c], w11 = a1[c + 1], w20 = a2[c], w21 = a2[c + 1];
            p1a = fmaf(x00, w10, fmaf(x01, w11, p1a));
            p2a = fmaf(x00, w20, fmaf(x01, w21, p2a));
            p1b = fmaf(x10, w10, fmaf(x11, w11, p1b));
            p2b = fmaf(x10, w20, fmaf(x11, w21, p2b));
        }
#pragma unroll
        for (int o = 1; o <= 2; o <<= 1) {
            p1a += __shfl_xor_sync(0xffffffffu, p1a, o);
            p2a += __shfl_xor_sync(0xffffffffu, p2a, o);
            p1b += __shfl_xor_sync(0xffffffffu, p1b, o);
            p2b += __shfl_xor_sync(0xffffffffu, p2b, o);
        }
        if ((lane & 3) == 0) {
            atomicAdd(&s1b[r0], p1a);
            atomicAdd(&s2b[r0], p2a);
            atomicAdd(&s1b[r0 + 8], p1b);
            atomicAdd(&s2b[r0 + 8], p2b);
        }
    }
    __syncthreads();
    if (tid < 128 && bm + tid < NN) {
        atomicAdd(&g_s1[(bm + tid) * 4 + h], s1b[tid]);
        atomicAdd(&g_s2[(bm + tid) * 4 + h], s2b[tid]);
    }
}

// ---------------- edge kernels ----------------------------------------------
__global__ void hist_kernel(const void* __restrict__ edge) {
    int e = blockIdx.x * blockDim.x + threadIdx.x;
    if (e >= EE) return;
    int src = load_edge(edge, e);
    atomicAdd(&g_deg[src], 1);
}

// 196-block atomic-offset allocator (4.96us measured).
__global__ __launch_bounds__(256) void offset_kernel() {
    __shared__ int wsum[8];
    __shared__ int sbase;
    const int tid = threadIdx.x, lane = tid & 31, wd = tid >> 5;
    const int n = blockIdx.x * 256 + tid;
    int d = (n < NN) ? g_deg[n] : 0;
    int v = d;
#pragma unroll
    for (int o = 1; o < 32; o <<= 1) {
        int u = __shfl_up_sync(0xffffffffu, v, o);
        if (lane >= o) v += u;
    }
    if (lane == 31) wsum[wd] = v;
    __syncthreads();
    if (tid == 0) {
        int run = 0;
#pragma unroll
        for (int i = 0; i < 8; i++) { int t = wsum[i]; wsum[i] = run; run += t; }
        sbase = atomicAdd(&g_alloc, run);
    }
    __syncthreads();
    int beg = sbase + wsum[wd] + v - d;   // exclusive prefix + block base
    if (n < NN) { g_rowbeg[n] = beg; g_cursor[n] = beg; }
}

__global__ __launch_bounds__(256) void score_scatter_kernel(const void* __restrict__ edge) {
    int e = blockIdx.x * blockDim.x + threadIdx.x;
    if (e >= EE) return;
    int src = load_edge(edge, e);
    int dst = load_edge(edge, (long long)EE + e);
    float4 v1 = *reinterpret_cast<const float4*>(g_s1 + src * 4);
    float4 v2 = *reinterpret_cast<const float4*>(g_s2 + dst * 4);
    float4 sc;
    {
        float s0 = v1.x + v2.x, s1 = v1.y + v2.y, s2 = v1.z + v2.z, s3 = v1.w + v2.w;
        s0 = (s0 >= 0.f ? s0 : ALPHA_L * s0) * INV_SCALE;
        s1 = (s1 >= 0.f ? s1 : ALPHA_L * s1) * INV_SCALE;
        s2 = (s2 >= 0.f ? s2 : ALPHA_L * s2) * INV_SCALE;
        s3 = (s3 >= 0.f ? s3 : ALPHA_L * s3) * INV_SCALE;
        sc = make_float4(__expf(s0), __expf(s1), __expf(s2), __expf(s3));
    }
    int pos = atomicAdd(&g_cursor[src], 1);
    g_dsts[pos] = dst;
    g_es[pos]   = sc;
}

// One block (128 thr) per node. fp16 X: thread t owns cols (2t,2t+1) of the
// lower 256 and (256+2t, 257+2t) of the upper 256 via two half2 loads/row.
__global__ __launch_bounds__(128) void agg_ln_kernel(
    const float* __restrict__ gain, const float* __restrict__ beta,
    float* __restrict__ out)
{
    const int n = blockIdx.x;
    const int t = threadIdx.x;
    const int beg = g_rowbeg[n], end = beg + g_deg[n];
    const int hs = t >> 6;                 // 0/1: head of first pair

    float ac0 = 0.f, ac1 = 0.f, ac2 = 0.f, ac3 = 0.f;
    float r0 = 0.f, r1 = 0.f, r2 = 0.f, r3 = 0.f;
    int d = 0; float4 e = make_float4(0.f, 0.f, 0.f, 0.f);
    if (beg < end) { d = __ldcs(&g_dsts[beg]); e = __ldcs(&g_es[beg]); }
    for (int i = beg; i < end; i++) {
        int dn = 0; float4 en;
        if (i + 1 < end) { dn = __ldcs(&g_dsts[i + 1]); en = __ldcs(&g_es[i + 1]); }
        else             { en = make_float4(0.f, 0.f, 0.f, 0.f); }
        const __half2* xr = reinterpret_cast<const __half2*>(g_Xh) + (size_t)d * 256;
        float2 f0 = __half22float2(xr[t]);
        float2 f1 = __half22float2(xr[128 + t]);
        float w0 = hs ? e.y : e.x;
        float w1 = hs ? e.w : e.z;
        ac0 = fmaf(w0, f0.x, ac0);
        ac1 = fmaf(w0, f0.y, ac1);
        ac2 = fmaf(w1, f1.x, ac2);
        ac3 = fmaf(w1, f1.y, ac3);
        r0 += e.x; r1 += e.y; r2 += e.z; r3 += e.w;
        d = dn; e = en;
    }
    float den0 = hs ? (r1 == 0.f ? 1.f : r1) : (r0 == 0.f ? 1.f : r0);
    float den1 = hs ? (r3 == 0.f ? 1.f : r3) : (r2 == 0.f ? 1.f : r2);
    float h0 = ac0 / den0, h1 = ac1 / den0;
    float h2 = ac2 / den1, h3 = ac3 / den1;

    float s  = h0 + h1 + h2 + h3;
    float ss = h0 * h0 + h1 * h1 + h2 * h2 + h3 * h3;
#pragma unroll
    for (int o = 16; o; o >>= 1) {
        s  += __shfl_xor_sync(0xffffffffu, s, o);
        ss += __shfl_xor_sync(0xffffffffu, ss, o);
    }
    __shared__ float rs[4], rss[4];
    int w = t >> 5;
    if ((t & 31) == 0) { rs[w] = s; rss[w] = ss; }
    __syncthreads();
    s  = rs[0] + rs[1] + rs[2] + rs[3];
    ss = rss[0] + rss[1] + rss[2] + rss[3];

    float mean = s * (1.f / 512.f);
    float var  = fmaxf((ss - 512.f * mean * mean) * (1.f / 511.f), 0.f);
    float inv  = 1.f / (sqrtf(var) + LN_EPS);

    float* orow = out + (size_t)n * COLS;
    int c0 = 2 * t, c2 = 256 + 2 * t;
    float v0 = gain[c0]     * (h0 - mean) * inv + beta[c0];
    float v1 = gain[c0 + 1] * (h1 - mean) * inv + beta[c0 + 1];
    float v2 = gain[c2]     * (h2 - mean) * inv + beta[c2];
    float v3 = gain[c2 + 1] * (h3 - mean) * inv + beta[c2 + 1];
    *reinterpret_cast<float2*>(orow + c0) =
        make_float2(v0 > 0.f ? v0 : expm1f(v0), v1 > 0.f ? v1 : expm1f(v1));
    *reinterpret_cast<float2*>(orow + c2) =
        make_float2(v2 > 0.f ? v2 : expm1f(v2), v3 > 0.f ? v3 : expm1f(v3));
}

// ---------------- launch -----------------------------------------------------
extern "C" void kernel_launch(void* const* d_in, const int* in_sizes, int n_in,
                              void* d_out, int out_size)
{
    (void)in_sizes; (void)n_in; (void)out_size;
    const void*  edge   = d_in[1];
    const float* emb    = (const float*)d_in[2];
    const float* W      = (const float*)d_in[3];
    const float* bias   = (const float*)d_in[4];
    const float* a_attn = (const float*)d_in[5];
    const float* gain   = (const float*)d_in[6];
    const float* beta   = (const float*)d_in[7];
    float* out = (float*)d_out;

    prep_kernel<<<PREP_A_BLOCKS, 256>>>(emb, W, (const int*)edge);

    dim3 gg(M_TILES, 8);
    gemm_mma_kernel<<<gg, 256>>>(bias, a_attn);

    hist_kernel<<<(EE + 255) / 256, 256>>>(edge);
    offset_kernel<<<OFF_BLOCKS, 256>>>();
    score_scatter_kernel<<<(EE + 255) / 256, 256>>>(edge);

    agg_ln_kernel<<<NN, 128>>>(gain, beta, out);
}

// round 11
// speedup vs baseline: 1.5227x; 1.1384x over previous
#include <cuda_runtime.h>
#include <cuda_fp16.h>
#include <math.h>
#include <stdint.h>

#define NN      50000
#define IN_F    256
#define HID     128
#define HEADS   4
#define EE      800000
#define COLS    (HEADS * HID)          // 512
#define ALPHA_L 0.2f
#define INV_SCALE 0.04419417382415922f // 1/sqrt(512)
#define LN_EPS  1e-6f

#define M_TILES ((NN + 127) / 128)     // 391
#define M_PAD   (M_TILES * 128)        // 50048

#define PREP_A_BLOCKS (M_PAD * (IN_F / 4) / 256)   // 12512 exactly
#define ZERO_BLOCKS   ((NN * HEADS + 255) / 256)   // 782
#define PREPB_BLOCKS  ((COLS * IN_F) / 256)        // 512
#define OFF_BLOCKS    ((NN + 255) / 256)           // 196

// ---------------- scratch (static device memory; no allocations) ------------
__device__ __half         g_Xh[(size_t)NN * COLS];    // 51.2 MB (L2-resident)
__device__ float          g_s1[NN * HEADS];
__device__ float          g_s2[NN * HEADS];
__device__ __half         g_Ah[(size_t)M_PAD * IN_F]; // A fp16 (25.6 MB)
__device__ __half         g_Bh[COLS * IN_F];          // W fp16 hi
__device__ __half         g_Bl[COLS * IN_F];          // W fp16 lo (residual)
__device__ float4         g_es[EE];
__device__ int            g_dsts[EE];
__device__ int            g_deg[NN];
__device__ int            g_rowbeg[NN];
__device__ int            g_cursor[NN];
__device__ int            g_alloc;
__device__ int            g_is64;

// ---------------- helpers ---------------------------------------------------
__device__ __forceinline__ int load_edge(const void* e, long long idx) {
    if (g_is64) return (int)((const long long*)e)[idx];
    return ((const int*)e)[idx];
}
__device__ __forceinline__ uint32_t smem_u32(const void* p) {
    uint32_t a;
    asm("{ .reg .u64 t; cvta.to.shared.u64 t, %1; cvt.u32.u64 %0, t; }"
        : "=r"(a) : "l"(p));
    return a;
}
__device__ __forceinline__ void ldsm4(uint32_t* r, uint32_t addr) {
    asm volatile("ldmatrix.sync.aligned.m8n8.x4.shared.b16 {%0,%1,%2,%3}, [%4];"
                 : "=r"(r[0]), "=r"(r[1]), "=r"(r[2]), "=r"(r[3]) : "r"(addr));
}
__device__ __forceinline__ void mma_f16(float* c, const uint32_t* a,
                                        const uint32_t* b) {
    asm volatile(
        "mma.sync.aligned.m16n8k16.row.col.f32.f16.f16.f32 "
        "{%0,%1,%2,%3}, {%4,%5,%6,%7}, {%8,%9}, {%0,%1,%2,%3};"
        : "+f"(c[0]), "+f"(c[1]), "+f"(c[2]), "+f"(c[3])
        : "r"(a[0]), "r"(a[1]), "r"(a[2]), "r"(a[3]), "r"(b[0]), "r"(b[1]));
}
__device__ __forceinline__ void cp16(uint32_t saddr, const void* gptr) {
    asm volatile("cp.async.cg.shared.global [%0], [%1], 16;"
                 :: "r"(saddr), "l"(gptr));
}
__device__ __forceinline__ void cp_commit() {
    asm volatile("cp.async.commit_group;" ::: "memory");
}
template <int N>
__device__ __forceinline__ void cp_wait() {
    asm volatile("cp.async.wait_group %0;" :: "n"(N) : "memory");
}
// SW64 swizzle for 64B rows: chunk16 index ^= (row>>1)&3
__device__ __forceinline__ uint32_t swz64(uint32_t row, uint32_t cbyte) {
    return row * 64 + (cbyte ^ (((row >> 1) & 3) << 4));
}
__device__ __forceinline__ uint32_t packh2(__half a, __half b) {
    return (uint32_t)__half_as_ushort(a) | ((uint32_t)__half_as_ushort(b) << 16);
}

// gemm smem: 2 stages x 16KB (A 8K, B hi 4K, B lo 4K) = 32KB static
#define ST_A    0
#define ST_B_HI 8192
#define ST_B_LO 12288
#define STAGE   16384
#define NCHUNK  8                      // 256 / 32

// ---------------- merged prep kernel -----------------------------------------
__global__ void prep_kernel(const float* __restrict__ emb,
                            const float* __restrict__ W,
                            const int*   __restrict__ edge_raw)
{
    const int b   = blockIdx.x;
    const int tid = threadIdx.x;

    // ---- detect (block 0, warp 0) + alloc counter reset ----
    if (b == 0 && tid < 32) {
        int bad = 0;
        for (int i = tid; i < 2048; i += 32)
            if (edge_raw[2 * i + 1] != 0) bad = 1;
        unsigned m = __ballot_sync(0xffffffffu, bad);
        if (tid == 0) g_is64 = (m == 0);
    }
    if (b == 0 && tid == 32) g_alloc = 0;
    // ---- zero s1/s2/deg ----
    if (b < ZERO_BLOCKS) {
        int i = b * 256 + tid;
        if (i < NN * HEADS) { g_s1[i] = 0.f; g_s2[i] = 0.f; }
        if (i < NN) g_deg[i] = 0;
    }
    // ---- W split into fp16 hi + residual ----
    if (b < PREPB_BLOCKS) {
        int i = b * 256 + tid;
        float w = W[i];
        __half hi = __float2half_rn(w);
        __half lo = __float2half_rn(w - __half2float(hi));
        g_Bh[i] = hi;
        g_Bl[i] = lo;
    }
    // ---- emb -> fp16 (every block) ----
    {
        int i = b * 256 + tid;                      // float4 granularity
        int row = i >> 6;
        int c4  = i & 63;
        float4 v = make_float4(0.f, 0.f, 0.f, 0.f);
        if (row < NN && row != 0)
            v = *reinterpret_cast<const float4*>(emb + (size_t)row * IN_F + c4 * 4);
        size_t off = (size_t)row * IN_F + c4 * 4;
        *reinterpret_cast<uint2*>(g_Ah + off) =
            make_uint2(packh2(__float2half_rn(v.x), __float2half_rn(v.y)),
                       packh2(__float2half_rn(v.z), __float2half_rn(v.w)));
    }
}

// ---------------- 2-pass split-fp16 HMMA GEMM, cp.async double-buffered ------
// X = A_fp16 * (Bhi + Blo)^T; error ~ 2^-11 (matches fp16 X-storage error).
// grid (391, 8): CTA = rows bm..bm+127, cols by*64..by*64+63.
// 8 warps in 4x2; warp tile 32x32. K in 8 chunks of 32, 2-stage pipeline.
__global__ __launch_bounds__(256, 2) void gemm_mma_kernel(
    const float* __restrict__ bias, const float* __restrict__ a_attn)
{
    __shared__ char smem[2 * STAGE];
    const uint32_t sb = smem_u32(smem);
    const int tid  = threadIdx.x;
    const int wid  = tid >> 5;
    const int lane = tid & 31;
    const int wm   = wid & 3;        // 0..3 (rows)
    const int wn   = wid >> 2;       // 0..1 (cols)
    const int bm   = blockIdx.x * 128;
    const int bn   = blockIdx.y * 64;
    const int h    = bn >> 7;        // head

    float acc[2][4][4];
#pragma unroll
    for (int i = 0; i < 2; i++)
#pragma unroll
        for (int j = 0; j < 4; j++)
#pragma unroll
            for (int r = 0; r < 4; r++) acc[i][j][r] = 0.f;

    const int a_row0 = tid >> 2;          // 0..63 (two rows: +0,+64)
    const int a_c16  = tid & 3;
    const int b_row  = tid >> 2;
    const int arow = wm * 32 + (lane & 15);
    const uint32_t a_klane = (uint32_t)((lane >> 4) << 4);
    const uint32_t a_xor   = (uint32_t)(((arow >> 1) & 3) << 4);
    const int m4   = lane >> 3;
    const int brow = wn * 32 + ((m4 >> 1) << 3) + (lane & 7);
    const uint32_t b_klane = (uint32_t)((m4 & 1) << 4);
    const uint32_t b_xor   = (uint32_t)(((brow >> 1) & 3) << 4);

    auto load_stage = [&](int kc, int buf) {
        uint32_t s0 = sb + buf * STAGE;
        // A: 128 rows x 32 k fp16 (each thread: 2 rows x 1 chunk)
#pragma unroll
        for (int l = 0; l < 2; l++) {
            int row = a_row0 + 64 * l;
            uint32_t so = swz64(row, a_c16 * 16);
            size_t gsrc = (size_t)(bm + row) * IN_F + kc * 32 + a_c16 * 8;
            cp16(s0 + ST_A + so, g_Ah + gsrc);
        }
        // B: 64 rows x 32 k, hi+lo
        {
            uint32_t so = swz64(b_row, a_c16 * 16);
            size_t gsrc = (size_t)(bn + b_row) * IN_F + kc * 32 + a_c16 * 8;
            cp16(s0 + ST_B_HI + so, g_Bh + gsrc);
            cp16(s0 + ST_B_LO + so, g_Bl + gsrc);
        }
        cp_commit();
    };

    load_stage(0, 0);

    for (int kc = 0; kc < NCHUNK; kc++) {
        if (kc + 1 < NCHUNK) load_stage(kc + 1, (kc + 1) & 1);
        if (kc + 1 < NCHUNK) cp_wait<1>(); else cp_wait<0>();
        __syncthreads();

        const uint32_t s0 = sb + (kc & 1) * STAGE;
        const uint32_t a_b    = s0 + ST_A    + arow * 64;
        const uint32_t b_hi_b = s0 + ST_B_HI + brow * 64;
        const uint32_t b_lo_b = s0 + ST_B_LO + brow * 64;
#pragma unroll
        for (int ks = 0; ks < 2; ks++) {
            const uint32_t akb = ((uint32_t)(ks * 32) + a_klane) ^ a_xor;
            const uint32_t bkb = ((uint32_t)(ks * 32) + b_klane) ^ b_xor;
            uint32_t af[2][4], bh[2][4], bl[2][4];
#pragma unroll
            for (int i = 0; i < 2; i++)
                ldsm4(af[i], a_b + i * 1024 + akb);
#pragma unroll
            for (int jp = 0; jp < 2; jp++)
                ldsm4(bh[jp], b_hi_b + jp * 1024 + bkb);
#pragma unroll
            for (int jp = 0; jp < 2; jp++)
                ldsm4(bl[jp], b_lo_b + jp * 1024 + bkb);
            // pass 1: A * Bhi
#pragma unroll
            for (int i = 0; i < 2; i++)
#pragma unroll
                for (int j = 0; j < 4; j++)
                    mma_f16(acc[i][j], af[i], &bh[j >> 1][(j & 1) * 2]);
            // pass 2: A * Blo
#pragma unroll
            for (int i = 0; i < 2; i++)
#pragma unroll
                for (int j = 0; j < 4; j++)
                    mma_f16(acc[i][j], af[i], &bl[j >> 1][(j & 1) * 2]);
        }
        __syncthreads();
    }

    // ---- epilogue: bias + fp16 X store + fused s1/s2 partials ---------------
    float* s1b = reinterpret_cast<float*>(smem);          // [128]
    float* s2b = reinterpret_cast<float*>(smem) + 128;    // [128]
    if (tid < 128) { s1b[tid] = 0.f; s2b[tid] = 0.f; }
    __syncthreads();

    const int chbase = bn - h * 128;                      // 0 or 64
    const float* a1 = a_attn + h * 2 * HID + chbase;
    const float* a2 = a1 + HID;
#pragma unroll
    for (int i = 0; i < 2; i++) {
        int r0 = wm * 32 + i * 16 + (lane >> 2);
        float p1a = 0.f, p2a = 0.f, p1b = 0.f, p2b = 0.f;
#pragma unroll
        for (int j = 0; j < 4; j++) {
            int c = wn * 32 + j * 8 + 2 * (lane & 3);
            float b0 = bias[bn + c], b1 = bias[bn + c + 1];
            float x00 = acc[i][j][0] + b0, x01 = acc[i][j][1] + b1;
            float x10 = acc[i][j][2] + b0, x11 = acc[i][j][3] + b1;
            int gr0 = bm + r0, gr1 = gr0 + 8;
            if (gr0 < NN)
                *reinterpret_cast<__half2*>(g_Xh + (size_t)gr0 * COLS + bn + c) =
                    __floats2half2_rn(x00, x01);
            if (gr1 < NN)
                *reinterpret_cast<__half2*>(g_Xh + (size_t)gr1 * COLS + bn + c) =
                    __floats2half2_rn(x10, x11);
            float w10 = a1[c], w11 = a1[c + 1], w20 = a2[c], w21 = a2[c + 1];
            p1a = fmaf(x00, w10, fmaf(x01, w11, p1a));
            p2a = fmaf(x00, w20, fmaf(x01, w21, p2a));
            p1b = fmaf(x10, w10, fmaf(x11, w11, p1b));
            p2b = fmaf(x10, w20, fmaf(x11, w21, p2b));
        }
#pragma unroll
        for (int o = 1; o <= 2; o <<= 1) {
            p1a += __shfl_xor_sync(0xffffffffu, p1a, o);
            p2a += __shfl_xor_sync(0xffffffffu, p2a, o);
            p1b += __shfl_xor_sync(0xffffffffu, p1b, o);
            p2b += __shfl_xor_sync(0xffffffffu, p2b, o);
        }
        if ((lane & 3) == 0) {
            atomicAdd(&s1b[r0], p1a);
            atomicAdd(&s2b[r0], p2a);
            atomicAdd(&s1b[r0 + 8], p1b);
            atomicAdd(&s2b[r0 + 8], p2b);
        }
    }
    __syncthreads();
    if (tid < 128 && bm + tid < NN) {
        atomicAdd(&g_s1[(bm + tid) * 4 + h], s1b[tid]);
        atomicAdd(&g_s2[(bm + tid) * 4 + h], s2b[tid]);
    }
}

// ---------------- edge kernels ----------------------------------------------
__global__ void hist_kernel(const void* __restrict__ edge) {
    int e = blockIdx.x * blockDim.x + threadIdx.x;
    if (e >= EE) return;
    int src = load_edge(edge, e);
    atomicAdd(&g_deg[src], 1);
}

// 196-block atomic-offset allocator (4.7us measured).
__global__ __launch_bounds__(256) void offset_kernel() {
    __shared__ int wsum[8];
    __shared__ int sbase;
    const int tid = threadIdx.x, lane = tid & 31, wd = tid >> 5;
    const int n = blockIdx.x * 256 + tid;
    int d = (n < NN) ? g_deg[n] : 0;
    int v = d;
#pragma unroll
    for (int o = 1; o < 32; o <<= 1) {
        int u = __shfl_up_sync(0xffffffffu, v, o);
        if (lane >= o) v += u;
    }
    if (lane == 31) wsum[wd] = v;
    __syncthreads();
    if (tid == 0) {
        int run = 0;
#pragma unroll
        for (int i = 0; i < 8; i++) { int t = wsum[i]; wsum[i] = run; run += t; }
        sbase = atomicAdd(&g_alloc, run);
    }
    __syncthreads();
    int beg = sbase + wsum[wd] + v - d;   // exclusive prefix + block base
    if (n < NN) { g_rowbeg[n] = beg; g_cursor[n] = beg; }
}

__global__ __launch_bounds__(256) void score_scatter_kernel(const void* __restrict__ edge) {
    int e = blockIdx.x * blockDim.x + threadIdx.x;
    if (e >= EE) return;
    int src = load_edge(edge, e);
    int dst = load_edge(edge, (long long)EE + e);
    float4 v1 = *reinterpret_cast<const float4*>(g_s1 + src * 4);
    float4 v2 = *reinterpret_cast<const float4*>(g_s2 + dst * 4);
    float4 sc;
    {
        float s0 = v1.x + v2.x, s1 = v1.y + v2.y, s2 = v1.z + v2.z, s3 = v1.w + v2.w;
        s0 = (s0 >= 0.f ? s0 : ALPHA_L * s0) * INV_SCALE;
        s1 = (s1 >= 0.f ? s1 : ALPHA_L * s1) * INV_SCALE;
        s2 = (s2 >= 0.f ? s2 : ALPHA_L * s2) * INV_SCALE;
        s3 = (s3 >= 0.f ? s3 : ALPHA_L * s3) * INV_SCALE;
        sc = make_float4(__expf(s0), __expf(s1), __expf(s2), __expf(s3));
    }
    int pos = atomicAdd(&g_cursor[src], 1);
    g_dsts[pos] = dst;
    g_es[pos]   = sc;
}

// One block (128 thr) per node. fp16 X: thread t owns cols (2t,2t+1) of the
// lower 256 and (256+2t, 257+2t) of the upper 256 via two half2 loads/row.
__global__ __launch_bounds__(128) void agg_ln_kernel(
    const float* __restrict__ gain, const float* __restrict__ beta,
    float* __restrict__ out)
{
    const int n = blockIdx.x;
    const int t = threadIdx.x;
    const int beg = g_rowbeg[n], end = beg + g_deg[n];
    const int hs = t >> 6;                 // 0/1: head of first pair

    float ac0 = 0.f, ac1 = 0.f, ac2 = 0.f, ac3 = 0.f;
    float r0 = 0.f, r1 = 0.f, r2 = 0.f, r3 = 0.f;
    int d = 0; float4 e = make_float4(0.f, 0.f, 0.f, 0.f);
    if (beg < end) { d = __ldcs(&g_dsts[beg]); e = __ldcs(&g_es[beg]); }
    for (int i = beg; i < end; i++) {
        int dn = 0; float4 en;
        if (i + 1 < end) { dn = __ldcs(&g_dsts[i + 1]); en = __ldcs(&g_es[i + 1]); }
        else             { en = make_float4(0.f, 0.f, 0.f, 0.f); }
        const __half2* xr = reinterpret_cast<const __half2*>(g_Xh) + (size_t)d * 256;
        float2 f0 = __half22float2(xr[t]);
        float2 f1 = __half22float2(xr[128 + t]);
        float w0 = hs ? e.y : e.x;
        float w1 = hs ? e.w : e.z;
        ac0 = fmaf(w0, f0.x, ac0);
        ac1 = fmaf(w0, f0.y, ac1);
        ac2 = fmaf(w1, f1.x, ac2);
        ac3 = fmaf(w1, f1.y, ac3);
        r0 += e.x; r1 += e.y; r2 += e.z; r3 += e.w;
        d = dn; e = en;
    }
    float den0 = hs ? (r1 == 0.f ? 1.f : r1) : (r0 == 0.f ? 1.f : r0);
    float den1 = hs ? (r3 == 0.f ? 1.f : r3) : (r2 == 0.f ? 1.f : r2);
    float h0 = ac0 / den0, h1 = ac1 / den0;
    float h2 = ac2 / den1, h3 = ac3 / den1;

    float s  = h0 + h1 + h2 + h3;
    float ss = h0 * h0 + h1 * h1 + h2 * h2 + h3 * h3;
#pragma unroll
    for (int o = 16; o; o >>= 1) {
        s  += __shfl_xor_sync(0xffffffffu, s, o);
        ss += __shfl_xor_sync(0xffffffffu, ss, o);
    }
    __shared__ float rs[4], rss[4];
    int w = t >> 5;
    if ((t & 31) == 0) { rs[w] = s; rss[w] = ss; }
    __syncthreads();
    s  = rs[0] + rs[1] + rs[2] + rs[3];
    ss = rss[0] + rss[1] + rss[2] + rss[3];

    float mean = s * (1.f / 512.f);
    float var  = fmaxf((ss - 512.f * mean * mean) * (1.f / 511.f), 0.f);
    float inv  = 1.f / (sqrtf(var) + LN_EPS);

    float* orow = out + (size_t)n * COLS;
    int c0 = 2 * t, c2 = 256 + 2 * t;
    float v0 = gain[c0]     * (h0 - mean) * inv + beta[c0];
    float v1 = gain[c0 + 1] * (h1 - mean) * inv + beta[c0 + 1];
    float v2 = gain[c2]     * (h2 - mean) * inv + beta[c2];
    float v3 = gain[c2 + 1] * (h3 - mean) * inv + beta[c2 + 1];
    *reinterpret_cast<float2*>(orow + c0) =
        make_float2(v0 > 0.f ? v0 : expm1f(v0), v1 > 0.f ? v1 : expm1f(v1));
    *reinterpret_cast<float2*>(orow + c2) =
        make_float2(v2 > 0.f ? v2 : expm1f(v2), v3 > 0.f ? v3 : expm1f(v3));
}

// ---------------- launch -----------------------------------------------------
extern "C" void kernel_launch(void* const* d_in, const int* in_sizes, int n_in,
                              void* d_out, int out_size)
{
    (void)in_sizes; (void)n_in; (void)out_size;
    const void*  edge   = d_in[1];
    const float* emb    = (const float*)d_in[2];
    const float* W      = (const float*)d_in[3];
    const float* bias   = (const float*)d_in[4];
    const float* a_attn = (const float*)d_in[5];
    const float* gain   = (const float*)d_in[6];
    const float* beta   = (const float*)d_in[7];
    float* out = (float*)d_out;

    prep_kernel<<<PREP_A_BLOCKS, 256>>>(emb, W, (const int*)edge);

    dim3 gg(M_TILES, 8);
    gemm_mma_kernel<<<gg, 256>>>(bias, a_attn);

    hist_kernel<<<(EE + 255) / 256, 256>>>(edge);
    offset_kernel<<<OFF_BLOCKS, 256>>>();
    score_scatter_kernel<<<(EE + 255) / 256, 256>>>(edge);

    agg_ln_kernel<<<NN, 128>>>(gain, beta, out);
}

// round 16
// speedup vs baseline: 1.5987x; 1.0499x over previous
#include <cuda_runtime.h>
#include <cuda_fp16.h>
#include <math.h>
#include <stdint.h>

#define NN      50000
#define IN_F    256
#define HID     128
#define HEADS   4
#define EE      800000
#define COLS    (HEADS * HID)          // 512
#define ALPHA_L 0.2f
#define INV_SCALE 0.04419417382415922f // 1/sqrt(512)
#define LN_EPS  1e-6f

#define M_TILES ((NN + 127) / 128)     // 391
#define M_PAD   (M_TILES * 128)        // 50048

#define PREP_A_BLOCKS (M_PAD * (IN_F / 4) / 256)   // 12512 exactly
#define ZERO_BLOCKS   ((NN * HEADS + 255) / 256)   // 782
#define PREPB_BLOCKS  ((COLS * IN_F) / 256)        // 512
#define OFF_BLOCKS    ((NN + 255) / 256)           // 196

// ---------------- scratch (static device memory; no allocations) ------------
__device__ __half         g_Xh[(size_t)NN * COLS];    // 51.2 MB (L2-resident)
__device__ float          g_s1[NN * HEADS];
__device__ float          g_s2[NN * HEADS];
__device__ __half         g_Ah[(size_t)M_PAD * IN_F]; // A fp16 (25.6 MB)
__device__ __half         g_Bh[COLS * IN_F];          // W fp16
__device__ float4         g_es[EE];
__device__ int            g_dsts[EE];
__device__ int            g_deg[NN];
__device__ int            g_rowbeg[NN];
__device__ int            g_cursor[NN];
__device__ int            g_alloc;
__device__ int            g_is64;

// ---------------- helpers ---------------------------------------------------
__device__ __forceinline__ int load_edge(const void* e, long long idx) {
    if (g_is64) return (int)((const long long*)e)[idx];
    return ((const int*)e)[idx];
}
__device__ __forceinline__ uint32_t smem_u32(const void* p) {
    uint32_t a;
    asm("{ .reg .u64 t; cvta.to.shared.u64 t, %1; cvt.u32.u64 %0, t; }"
        : "=r"(a) : "l"(p));
    return a;
}
__device__ __forceinline__ void ldsm4(uint32_t* r, uint32_t addr) {
    asm volatile("ldmatrix.sync.aligned.m8n8.x4.shared.b16 {%0,%1,%2,%3}, [%4];"
                 : "=r"(r[0]), "=r"(r[1]), "=r"(r[2]), "=r"(r[3]) : "r"(addr));
}
__device__ __forceinline__ void mma_f16(float* c, const uint32_t* a,
                                        const uint32_t* b) {
    asm volatile(
        "mma.sync.aligned.m16n8k16.row.col.f32.f16.f16.f32 "
        "{%0,%1,%2,%3}, {%4,%5,%6,%7}, {%8,%9}, {%0,%1,%2,%3};"
        : "+f"(c[0]), "+f"(c[1]), "+f"(c[2]), "+f"(c[3])
        : "r"(a[0]), "r"(a[1]), "r"(a[2]), "r"(a[3]), "r"(b[0]), "r"(b[1]));
}
__device__ __forceinline__ void cp16(uint32_t saddr, const void* gptr) {
    asm volatile("cp.async.cg.shared.global [%0], [%1], 16;"
                 :: "r"(saddr), "l"(gptr));
}
__device__ __forceinline__ void cp_commit() {
    asm volatile("cp.async.commit_group;" ::: "memory");
}
template <int N>
__device__ __forceinline__ void cp_wait() {
    asm volatile("cp.async.wait_group %0;" :: "n"(N) : "memory");
}
// SW64 swizzle for 64B rows: chunk16 index ^= (row>>1)&3
__device__ __forceinline__ uint32_t swz64(uint32_t row, uint32_t cbyte) {
    return row * 64 + (cbyte ^ (((row >> 1) & 3) << 4));
}
__device__ __forceinline__ uint32_t packh2(__half a, __half b) {
    return (uint32_t)__half_as_ushort(a) | ((uint32_t)__half_as_ushort(b) << 16);
}

// gemm smem: 2 stages x 12KB (A 8K, B 4K) = 24KB static
#define ST_A    0
#define ST_B    8192
#define STAGE   12288
#define NCHUNK  8                      // 256 / 32

// ---------------- merged prep kernel -----------------------------------------
__global__ void prep_kernel(const float* __restrict__ emb,
                            const float* __restrict__ W,
                            const int*   __restrict__ edge_raw)
{
    const int b   = blockIdx.x;
    const int tid = threadIdx.x;

    // ---- detect (block 0, warp 0) + alloc counter reset ----
    if (b == 0 && tid < 32) {
        int bad = 0;
        for (int i = tid; i < 2048; i += 32)
            if (edge_raw[2 * i + 1] != 0) bad = 1;
        unsigned m = __ballot_sync(0xffffffffu, bad);
        if (tid == 0) g_is64 = (m == 0);
    }
    if (b == 0 && tid == 32) g_alloc = 0;
    // ---- zero s1/s2/deg ----
    if (b < ZERO_BLOCKS) {
        int i = b * 256 + tid;
        if (i < NN * HEADS) { g_s1[i] = 0.f; g_s2[i] = 0.f; }
        if (i < NN) g_deg[i] = 0;
    }
    // ---- W -> fp16 ----
    if (b < PREPB_BLOCKS) {
        int i = b * 256 + tid;
        g_Bh[i] = __float2half_rn(W[i]);
    }
    // ---- emb -> fp16 (every block) ----
    {
        int i = b * 256 + tid;                      // float4 granularity
        int row = i >> 6;
        int c4  = i & 63;
        float4 v = make_float4(0.f, 0.f, 0.f, 0.f);
        if (row < NN && row != 0)
            v = *reinterpret_cast<const float4*>(emb + (size_t)row * IN_F + c4 * 4);
        size_t off = (size_t)row * IN_F + c4 * 4;
        *reinterpret_cast<uint2*>(g_Ah + off) =
            make_uint2(packh2(__float2half_rn(v.x), __float2half_rn(v.y)),
                       packh2(__float2half_rn(v.z), __float2half_rn(v.w)));
    }
}

// ---------------- single-pass fp16 HMMA GEMM, cp.async double-buffered -------
// X = A_fp16 * B_fp16^T; three independent 2^-11 rounding sources total
// (A, B, X-store) -> calibrated output rel_err ~ 2.1e-4 * sqrt(3) = 3.6e-4.
// grid (391, 8): CTA = rows bm..bm+127, cols by*64..by*64+63.
// 8 warps in 4x2; warp tile 32x32. K in 8 chunks of 32, 2-stage pipeline.
__global__ __launch_bounds__(256, 2) void gemm_mma_kernel(
    const float* __restrict__ bias, const float* __restrict__ a_attn)
{
    __shared__ char smem[2 * STAGE];
    const uint32_t sb = smem_u32(smem);
    const int tid  = threadIdx.x;
    const int wid  = tid >> 5;
    const int lane = tid & 31;
    const int wm   = wid & 3;        // 0..3 (rows)
    const int wn   = wid >> 2;       // 0..1 (cols)
    const int bm   = blockIdx.x * 128;
    const int bn   = blockIdx.y * 64;
    const int h    = bn >> 7;        // head

    float acc[2][4][4];
#pragma unroll
    for (int i = 0; i < 2; i++)
#pragma unroll
        for (int j = 0; j < 4; j++)
#pragma unroll
            for (int r = 0; r < 4; r++) acc[i][j][r] = 0.f;

    const int a_row0 = tid >> 2;          // 0..63 (two rows: +0,+64)
    const int a_c16  = tid & 3;
    const int b_row  = tid >> 2;
    const int arow = wm * 32 + (lane & 15);
    const uint32_t a_klane = (uint32_t)((lane >> 4) << 4);
    const uint32_t a_xor   = (uint32_t)(((arow >> 1) & 3) << 4);
    const int m4   = lane >> 3;
    const int brow = wn * 32 + ((m4 >> 1) << 3) + (lane & 7);
    const uint32_t b_klane = (uint32_t)((m4 & 1) << 4);
    const uint32_t b_xor   = (uint32_t)(((brow >> 1) & 3) << 4);

    auto load_stage = [&](int kc, int buf) {
        uint32_t s0 = sb + buf * STAGE;
        // A: 128 rows x 32 k fp16 (each thread: 2 rows x 1 chunk)
#pragma unroll
        for (int l = 0; l < 2; l++) {
            int row = a_row0 + 64 * l;
            uint32_t so = swz64(row, a_c16 * 16);
            size_t gsrc = (size_t)(bm + row) * IN_F + kc * 32 + a_c16 * 8;
            cp16(s0 + ST_A + so, g_Ah + gsrc);
        }
        // B: 64 rows x 32 k
        {
            uint32_t so = swz64(b_row, a_c16 * 16);
            size_t gsrc = (size_t)(bn + b_row) * IN_F + kc * 32 + a_c16 * 8;
            cp16(s0 + ST_B + so, g_Bh + gsrc);
        }
        cp_commit();
    };

    load_stage(0, 0);

    for (int kc = 0; kc < NCHUNK; kc++) {
        if (kc + 1 < NCHUNK) load_stage(kc + 1, (kc + 1) & 1);
        if (kc + 1 < NCHUNK) cp_wait<1>(); else cp_wait<0>();
        __syncthreads();

        const uint32_t s0 = sb + (kc & 1) * STAGE;
        const uint32_t a_b = s0 + ST_A + arow * 64;
        const uint32_t b_b = s0 + ST_B + brow * 64;
#pragma unroll
        for (int ks = 0; ks < 2; ks++) {
            const uint32_t akb = ((uint32_t)(ks * 32) + a_klane) ^ a_xor;
            const uint32_t bkb = ((uint32_t)(ks * 32) + b_klane) ^ b_xor;
            uint32_t af[2][4], bf[2][4];
#pragma unroll
            for (int i = 0; i < 2; i++)
                ldsm4(af[i], a_b + i * 1024 + akb);
#pragma unroll
            for (int jp = 0; jp < 2; jp++)
                ldsm4(bf[jp], b_b + jp * 1024 + bkb);
#pragma unroll
            for (int i = 0; i < 2; i++)
#pragma unroll
                for (int j = 0; j < 4; j++)
                    mma_f16(acc[i][j], af[i], &bf[j >> 1][(j & 1) * 2]);
        }
        __syncthreads();
    }

    // ---- epilogue: bias + fp16 X store + fused s1/s2 partials ---------------
    float* s1b = reinterpret_cast<float*>(smem);          // [128]
    float* s2b = reinterpret_cast<float*>(smem) + 128;    // [128]
    if (tid < 128) { s1b[tid] = 0.f; s2b[tid] = 0.f; }
    __syncthreads();

    const int chbase = bn - h * 128;                      // 0 or 64
    const float* a1 = a_attn + h * 2 * HID + chbase;
    const float* a2 = a1 + HID;
#pragma unroll
    for (int i = 0; i < 2; i++) {
        int r0 = wm * 32 + i * 16 + (lane >> 2);
        float p1a = 0.f, p2a = 0.f, p1b = 0.f, p2b = 0.f;
#pragma unroll
        for (int j = 0; j < 4; j++) {
            int c = wn * 32 + j * 8 + 2 * (lane & 3);
            float b0 = bias[bn + c], b1 = bias[bn + c + 1];
            float x00 = acc[i][j][0] + b0, x01 = acc[i][j][1] + b1;
            float x10 = acc[i][j][2] + b0, x11 = acc[i][j][3] + b1;
            int gr0 = bm + r0, gr1 = gr0 + 8;
            if (gr0 < NN)
                *reinterpret_cast<__half2*>(g_Xh + (size_t)gr0 * COLS + bn + c) =
                    __floats2half2_rn(x00, x01);
            if (gr1 < NN)
                *reinterpret_cast<__half2*>(g_Xh + (size_t)gr1 * COLS + bn + c) =
                    __floats2half2_rn(x10, x11);
            float w10 = a1[c], w11 = a1[c + 1], w20 = a2[c], w21 = a2[c + 1];
            p1a = fmaf(x00, w10, fmaf(x01, w11, p1a));
            p2a = fmaf(x00, w20, fmaf(x01, w21, p2a));
            p1b = fmaf(x10, w10, fmaf(x11, w11, p1b));
            p2b = fmaf(x10, w20, fmaf(x11, w21, p2b));
        }
#pragma unroll
        for (int o = 1; o <= 2; o <<= 1) {
            p1a += __shfl_xor_sync(0xffffffffu, p1a, o);
            p2a += __shfl_xor_sync(0xffffffffu, p2a, o);
            p1b += __shfl_xor_sync(0xffffffffu, p1b, o);
            p2b += __shfl_xor_sync(0xffffffffu, p2b, o);
        }
        if ((lane & 3) == 0) {
            atomicAdd(&s1b[r0], p1a);
            atomicAdd(&s2b[r0], p2a);
            atomicAdd(&s1b[r0 + 8], p1b);
            atomicAdd(&s2b[r0 + 8], p2b);
        }
    }
    __syncthreads();
    if (tid < 128 && bm + tid < NN) {
        atomicAdd(&g_s1[(bm + tid) * 4 + h], s1b[tid]);
        atomicAdd(&g_s2[(bm + tid) * 4 + h], s2b[tid]);
    }
}

// ---------------- edge kernels ----------------------------------------------
__global__ void hist_kernel(const void* __restrict__ edge) {
    int e = blockIdx.x * blockDim.x + threadIdx.x;
    if (e >= EE) return;
    int src = load_edge(edge, e);
    atomicAdd(&g_deg[src], 1);
}

// 196-block atomic-offset allocator (4.7us measured).
__global__ __launch_bounds__(256) void offset_kernel() {
    __shared__ int wsum[8];
    __shared__ int sbase;
    const int tid = threadIdx.x, lane = tid & 31, wd = tid >> 5;
    const int n = blockIdx.x * 256 + tid;
    int d = (n < NN) ? g_deg[n] : 0;
    int v = d;
#pragma unroll
    for (int o = 1; o < 32; o <<= 1) {
        int u = __shfl_up_sync(0xffffffffu, v, o);
        if (lane >= o) v += u;
    }
    if (lane == 31) wsum[wd] = v;
    __syncthreads();
    if (tid == 0) {
        int run = 0;
#pragma unroll
        for (int i = 0; i < 8; i++) { int t = wsum[i]; wsum[i] = run; run += t; }
        sbase = atomicAdd(&g_alloc, run);
    }
    __syncthreads();
    int beg = sbase + wsum[wd] + v - d;   // exclusive prefix + block base
    if (n < NN) { g_rowbeg[n] = beg; g_cursor[n] = beg; }
}

__global__ __launch_bounds__(256) void score_scatter_kernel(const void* __restrict__ edge) {
    int e = blockIdx.x * blockDim.x + threadIdx.x;
    if (e >= EE) return;
    int src = load_edge(edge, e);
    int dst = load_edge(edge, (long long)EE + e);
    float4 v1 = *reinterpret_cast<const float4*>(g_s1 + src * 4);
    float4 v2 = *reinterpret_cast<const float4*>(g_s2 + dst * 4);
    float4 sc;
    {
        float s0 = v1.x + v2.x, s1 = v1.y + v2.y, s2 = v1.z + v2.z, s3 = v1.w + v2.w;
        s0 = (s0 >= 0.f ? s0 : ALPHA_L * s0) * INV_SCALE;
        s1 = (s1 >= 0.f ? s1 : ALPHA_L * s1) * INV_SCALE;
        s2 = (s2 >= 0.f ? s2 : ALPHA_L * s2) * INV_SCALE;
        s3 = (s3 >= 0.f ? s3 : ALPHA_L * s3) * INV_SCALE;
        sc = make_float4(__expf(s0), __expf(s1), __expf(s2), __expf(s3));
    }
    int pos = atomicAdd(&g_cursor[src], 1);
    g_dsts[pos] = dst;
    g_es[pos]   = sc;
}

// One block (128 thr) per node. fp16 X: thread t owns cols (2t,2t+1) of the
// lower 256 and (256+2t, 257+2t) of the upper 256 via two half2 loads/row.
__global__ __launch_bounds__(128) void agg_ln_kernel(
    const float* __restrict__ gain, const float* __restrict__ beta,
    float* __restrict__ out)
{
    const int n = blockIdx.x;
    const int t = threadIdx.x;
    const int beg = g_rowbeg[n], end = beg + g_deg[n];
    const int hs = t >> 6;                 // 0/1: head of first pair

    float ac0 = 0.f, ac1 = 0.f, ac2 = 0.f, ac3 = 0.f;
    float r0 = 0.f, r1 = 0.f, r2 = 0.f, r3 = 0.f;
    int d = 0; float4 e = make_float4(0.f, 0.f, 0.f, 0.f);
    if (beg < end) { d = __ldcs(&g_dsts[beg]); e = __ldcs(&g_es[beg]); }
    for (int i = beg; i < end; i++) {
        int dn = 0; float4 en;
        if (i + 1 < end) { dn = __ldcs(&g_dsts[i + 1]); en = __ldcs(&g_es[i + 1]); }
        else             { en = make_float4(0.f, 0.f, 0.f, 0.f); }
        const __half2* xr = reinterpret_cast<const __half2*>(g_Xh) + (size_t)d * 256;
        float2 f0 = __half22float2(xr[t]);
        float2 f1 = __half22float2(xr[128 + t]);
        float w0 = hs ? e.y : e.x;
        float w1 = hs ? e.w : e.z;
        ac0 = fmaf(w0, f0.x, ac0);
        ac1 = fmaf(w0, f0.y, ac1);
        ac2 = fmaf(w1, f1.x, ac2);
        ac3 = fmaf(w1, f1.y, ac3);
        r0 += e.x; r1 += e.y; r2 += e.z; r3 += e.w;
        d = dn; e = en;
    }
    float den0 = hs ? (r1 == 0.f ? 1.f : r1) : (r0 == 0.f ? 1.f : r0);
    float den1 = hs ? (r3 == 0.f ? 1.f : r3) : (r2 == 0.f ? 1.f : r2);
    float h0 = ac0 / den0, h1 = ac1 / den0;
    float h2 = ac2 / den1, h3 = ac3 / den1;

    float s  = h0 + h1 + h2 + h3;
    float ss = h0 * h0 + h1 * h1 + h2 * h2 + h3 * h3;
#pragma unroll
    for (int o = 16; o; o >>= 1) {
        s  += __shfl_xor_sync(0xffffffffu, s, o);
        ss += __shfl_xor_sync(0xffffffffu, ss, o);
    }
    __shared__ float rs[4], rss[4];
    int w = t >> 5;
    if ((t & 31) == 0) { rs[w] = s; rss[w] = ss; }
    __syncthreads();
    s  = rs[0] + rs[1] + rs[2] + rs[3];
    ss = rss[0] + rss[1] + rss[2] + rss[3];

    float mean = s * (1.f / 512.f);
    float var  = fmaxf((ss - 512.f * mean * mean) * (1.f / 511.f), 0.f);
    float inv  = 1.f / (sqrtf(var) + LN_EPS);

    float* orow = out + (size_t)n * COLS;
    int c0 = 2 * t, c2 = 256 + 2 * t;
    float v0 = gain[c0]     * (h0 - mean) * inv + beta[c0];
    float v1 = gain[c0 + 1] * (h1 - mean) * inv + beta[c0 + 1];
    float v2 = gain[c2]     * (h2 - mean) * inv + beta[c2];
    float v3 = gain[c2 + 1] * (h3 - mean) * inv + beta[c2 + 1];
    *reinterpret_cast<float2*>(orow + c0) =
        make_float2(v0 > 0.f ? v0 : expm1f(v0), v1 > 0.f ? v1 : expm1f(v1));
    *reinterpret_cast<float2*>(orow + c2) =
        make_float2(v2 > 0.f ? v2 : expm1f(v2), v3 > 0.f ? v3 : expm1f(v3));
}

// ---------------- launch -----------------------------------------------------
extern "C" void kernel_launch(void* const* d_in, const int* in_sizes, int n_in,
                              void* d_out, int out_size)
{
    (void)in_sizes; (void)n_in; (void)out_size;
    const void*  edge   = d_in[1];
    const float* emb    = (const float*)d_in[2];
    const float* W      = (const float*)d_in[3];
    const float* bias   = (const float*)d_in[4];
    const float* a_attn = (const float*)d_in[5];
    const float* gain   = (const float*)d_in[6];
    const float* beta   = (const float*)d_in[7];
    float* out = (float*)d_out;

    prep_kernel<<<PREP_A_BLOCKS, 256>>>(emb, W, (const int*)edge);

    dim3 gg(M_TILES, 8);
    gemm_mma_kernel<<<gg, 256>>>(bias, a_attn);

    hist_kernel<<<(EE + 255) / 256, 256>>>(edge);
    offset_kernel<<<OFF_BLOCKS, 256>>>();
    score_scatter_kernel<<<(EE + 255) / 256, 256>>>(edge);

    agg_ln_kernel<<<NN, 128>>>(gain, beta, out);
}

// round 17
// speedup vs baseline: 1.6259x; 1.0170x over previous
#include <cuda_runtime.h>
#include <cuda_fp16.h>
#include <math.h>
#include <stdint.h>

#define NN      50000
#define IN_F    256
#define HID     128
#define HEADS   4
#define EE      800000
#define COLS    (HEADS * HID)          // 512
#define ALPHA_L 0.2f
#define INV_SCALE 0.04419417382415922f // 1/sqrt(512)
#define LN_EPS  1e-6f

#define M_TILES ((NN + 127) / 128)     // 391
#define M_PAD   (M_TILES * 128)        // 50048

#define PREP_A_BLOCKS (M_PAD * (IN_F / 4) / 256)   // 12512 exactly
#define ZERO_BLOCKS   ((NN * HEADS + 255) / 256)   // 782
#define PREPB_BLOCKS  ((COLS * IN_F) / 256)        // 512
#define OFF_BLOCKS    ((NN + 255) / 256)           // 196

// ---------------- scratch (static device memory; no allocations) ------------
__device__ __half         g_Xh[(size_t)NN * COLS];    // 51.2 MB (L2-resident)
__device__ float          g_s1[NN * HEADS];
__device__ float          g_s2[NN * HEADS];
__device__ __half         g_Ah[(size_t)M_PAD * IN_F]; // A fp16 (25.6 MB)
__device__ __half         g_Bh[COLS * IN_F];          // W fp16
__device__ float4         g_es[EE];
__device__ int            g_dsts[EE];
__device__ int            g_deg[NN];
__device__ int            g_rowbeg[NN];
__device__ int            g_cursor[NN];
__device__ int            g_alloc;
__device__ int            g_is64;

// ---------------- helpers ---------------------------------------------------
__device__ __forceinline__ int load_edge(const void* e, long long idx) {
    if (g_is64) return (int)((const long long*)e)[idx];
    return ((const int*)e)[idx];
}
__device__ __forceinline__ uint32_t smem_u32(const void* p) {
    uint32_t a;
    asm("{ .reg .u64 t; cvta.to.shared.u64 t, %1; cvt.u32.u64 %0, t; }"
        : "=r"(a) : "l"(p));
    return a;
}
__device__ __forceinline__ void ldsm4(uint32_t* r, uint32_t addr) {
    asm volatile("ldmatrix.sync.aligned.m8n8.x4.shared.b16 {%0,%1,%2,%3}, [%4];"
                 : "=r"(r[0]), "=r"(r[1]), "=r"(r[2]), "=r"(r[3]) : "r"(addr));
}
__device__ __forceinline__ void mma_f16(float* c, const uint32_t* a,
                                        const uint32_t* b) {
    asm volatile(
        "mma.sync.aligned.m16n8k16.row.col.f32.f16.f16.f32 "
        "{%0,%1,%2,%3}, {%4,%5,%6,%7}, {%8,%9}, {%0,%1,%2,%3};"
        : "+f"(c[0]), "+f"(c[1]), "+f"(c[2]), "+f"(c[3])
        : "r"(a[0]), "r"(a[1]), "r"(a[2]), "r"(a[3]), "r"(b[0]), "r"(b[1]));
}
__device__ __forceinline__ void cp16(uint32_t saddr, const void* gptr) {
    asm volatile("cp.async.cg.shared.global [%0], [%1], 16;"
                 :: "r"(saddr), "l"(gptr));
}
__device__ __forceinline__ void cp_commit() {
    asm volatile("cp.async.commit_group;" ::: "memory");
}
template <int N>
__device__ __forceinline__ void cp_wait() {
    asm volatile("cp.async.wait_group %0;" :: "n"(N) : "memory");
}
// SW64 swizzle for 64B rows: chunk16 index ^= (row>>1)&3
__device__ __forceinline__ uint32_t swz64(uint32_t row, uint32_t cbyte) {
    return row * 64 + (cbyte ^ (((row >> 1) & 3) << 4));
}
__device__ __forceinline__ uint32_t packh2(__half a, __half b) {
    return (uint32_t)__half_as_ushort(a) | ((uint32_t)__half_as_ushort(b) << 16);
}

// gemm smem: 2 stages x 12KB (A 8K, B 4K) = 24KB static
#define ST_A    0
#define ST_B    8192
#define STAGE   12288
#define NCHUNK  8                      // 256 / 32

// ---------------- merged prep kernel -----------------------------------------
__global__ void prep_kernel(const float* __restrict__ emb,
                            const float* __restrict__ W,
                            const int*   __restrict__ edge_raw)
{
    const int b   = blockIdx.x;
    const int tid = threadIdx.x;

    // ---- detect (block 0, warp 0) + alloc counter reset ----
    if (b == 0 && tid < 32) {
        int bad = 0;
        for (int i = tid; i < 2048; i += 32)
            if (edge_raw[2 * i + 1] != 0) bad = 1;
        unsigned m = __ballot_sync(0xffffffffu, bad);
        if (tid == 0) g_is64 = (m == 0);
    }
    if (b == 0 && tid == 32) g_alloc = 0;
    // ---- zero s1/s2/deg ----
    if (b < ZERO_BLOCKS) {
        int i = b * 256 + tid;
        if (i < NN * HEADS) { g_s1[i] = 0.f; g_s2[i] = 0.f; }
        if (i < NN) g_deg[i] = 0;
    }
    // ---- W -> fp16 ----
    if (b < PREPB_BLOCKS) {
        int i = b * 256 + tid;
        g_Bh[i] = __float2half_rn(W[i]);
    }
    // ---- emb -> fp16 (every block) ----
    {
        int i = b * 256 + tid;                      // float4 granularity
        int row = i >> 6;
        int c4  = i & 63;
        float4 v = make_float4(0.f, 0.f, 0.f, 0.f);
        if (row < NN && row != 0)
            v = *reinterpret_cast<const float4*>(emb + (size_t)row * IN_F + c4 * 4);
        size_t off = (size_t)row * IN_F + c4 * 4;
        *reinterpret_cast<uint2*>(g_Ah + off) =
            make_uint2(packh2(__float2half_rn(v.x), __float2half_rn(v.y)),
                       packh2(__float2half_rn(v.z), __float2half_rn(v.w)));
    }
}

// ---------------- single-pass fp16 HMMA GEMM, cp.async double-buffered -------
__global__ __launch_bounds__(256, 2) void gemm_mma_kernel(
    const float* __restrict__ bias, const float* __restrict__ a_attn)
{
    __shared__ char smem[2 * STAGE];
    const uint32_t sb = smem_u32(smem);
    const int tid  = threadIdx.x;
    const int wid  = tid >> 5;
    const int lane = tid & 31;
    const int wm   = wid & 3;        // 0..3 (rows)
    const int wn   = wid >> 2;       // 0..1 (cols)
    const int bm   = blockIdx.x * 128;
    const int bn   = blockIdx.y * 64;
    const int h    = bn >> 7;        // head

    float acc[2][4][4];
#pragma unroll
    for (int i = 0; i < 2; i++)
#pragma unroll
        for (int j = 0; j < 4; j++)
#pragma unroll
            for (int r = 0; r < 4; r++) acc[i][j][r] = 0.f;

    const int a_row0 = tid >> 2;          // 0..63 (two rows: +0,+64)
    const int a_c16  = tid & 3;
    const int b_row  = tid >> 2;
    const int arow = wm * 32 + (lane & 15);
    const uint32_t a_klane = (uint32_t)((lane >> 4) << 4);
    const uint32_t a_xor   = (uint32_t)(((arow >> 1) & 3) << 4);
    const int m4   = lane >> 3;
    const int brow = wn * 32 + ((m4 >> 1) << 3) + (lane & 7);
    const uint32_t b_klane = (uint32_t)((m4 & 1) << 4);
    const uint32_t b_xor   = (uint32_t)(((brow >> 1) & 3) << 4);

    auto load_stage = [&](int kc, int buf) {
        uint32_t s0 = sb + buf * STAGE;
#pragma unroll
        for (int l = 0; l < 2; l++) {
            int row = a_row0 + 64 * l;
            uint32_t so = swz64(row, a_c16 * 16);
            size_t gsrc = (size_t)(bm + row) * IN_F + kc * 32 + a_c16 * 8;
            cp16(s0 + ST_A + so, g_Ah + gsrc);
        }
        {
            uint32_t so = swz64(b_row, a_c16 * 16);
            size_t gsrc = (size_t)(bn + b_row) * IN_F + kc * 32 + a_c16 * 8;
            cp16(s0 + ST_B + so, g_Bh + gsrc);
        }
        cp_commit();
    };

    load_stage(0, 0);

    for (int kc = 0; kc < NCHUNK; kc++) {
        if (kc + 1 < NCHUNK) load_stage(kc + 1, (kc + 1) & 1);
        if (kc + 1 < NCHUNK) cp_wait<1>(); else cp_wait<0>();
        __syncthreads();

        const uint32_t s0 = sb + (kc & 1) * STAGE;
        const uint32_t a_b = s0 + ST_A + arow * 64;
        const uint32_t b_b = s0 + ST_B + brow * 64;
#pragma unroll
        for (int ks = 0; ks < 2; ks++) {
            const uint32_t akb = ((uint32_t)(ks * 32) + a_klane) ^ a_xor;
            const uint32_t bkb = ((uint32_t)(ks * 32) + b_klane) ^ b_xor;
            uint32_t af[2][4], bf[2][4];
#pragma unroll
            for (int i = 0; i < 2; i++)
                ldsm4(af[i], a_b + i * 1024 + akb);
#pragma unroll
            for (int jp = 0; jp < 2; jp++)
                ldsm4(bf[jp], b_b + jp * 1024 + bkb);
#pragma unroll
            for (int i = 0; i < 2; i++)
#pragma unroll
                for (int j = 0; j < 4; j++)
                    mma_f16(acc[i][j], af[i], &bf[j >> 1][(j & 1) * 2]);
        }
        __syncthreads();
    }

    // ---- epilogue: bias + fp16 X store + fused s1/s2 partials ---------------
    float* s1b = reinterpret_cast<float*>(smem);          // [128]
    float* s2b = reinterpret_cast<float*>(smem) + 128;    // [128]
    if (tid < 128) { s1b[tid] = 0.f; s2b[tid] = 0.f; }
    __syncthreads();

    const int chbase = bn - h * 128;                      // 0 or 64
    const float* a1 = a_attn + h * 2 * HID + chbase;
    const float* a2 = a1 + HID;
#pragma unroll
    for (int i = 0; i < 2; i++) {
        int r0 = wm * 32 + i * 16 + (lane >> 2);
        float p1a = 0.f, p2a = 0.f, p1b = 0.f, p2b = 0.f;
#pragma unroll
        for (int j = 0; j < 4; j++) {
            int c = wn * 32 + j * 8 + 2 * (lane & 3);
            float b0 = bias[bn + c], b1 = bias[bn + c + 1];
            float x00 = acc[i][j][0] + b0, x01 = acc[i][j][1] + b1;
            float x10 = acc[i][j][2] + b0, x11 = acc[i][j][3] + b1;
            int gr0 = bm + r0, gr1 = gr0 + 8;
            if (gr0 < NN)
                *reinterpret_cast<__half2*>(g_Xh + (size_t)gr0 * COLS + bn + c) =
                    __floats2half2_rn(x00, x01);
            if (gr1 < NN)
                *reinterpret_cast<__half2*>(g_Xh + (size_t)gr1 * COLS + bn + c) =
                    __floats2half2_rn(x10, x11);
            float w10 = a1[c], w11 = a1[c + 1], w20 = a2[c], w21 = a2[c + 1];
            p1a = fmaf(x00, w10, fmaf(x01, w11, p1a));
            p2a = fmaf(x00, w20, fmaf(x01, w21, p2a));
            p1b = fmaf(x10, w10, fmaf(x11, w11, p1b));
            p2b = fmaf(x10, w20, fmaf(x11, w21, p2b));
        }
#pragma unroll
        for (int o = 1; o <= 2; o <<= 1) {
            p1a += __shfl_xor_sync(0xffffffffu, p1a, o);
            p2a += __shfl_xor_sync(0xffffffffu, p2a, o);
            p1b += __shfl_xor_sync(0xffffffffu, p1b, o);
            p2b += __shfl_xor_sync(0xffffffffu, p2b, o);
        }
        if ((lane & 3) == 0) {
            atomicAdd(&s1b[r0], p1a);
            atomicAdd(&s2b[r0], p2a);
            atomicAdd(&s1b[r0 + 8], p1b);
            atomicAdd(&s2b[r0 + 8], p2b);
        }
    }
    __syncthreads();
    if (tid < 128 && bm + tid < NN) {
        atomicAdd(&g_s1[(bm + tid) * 4 + h], s1b[tid]);
        atomicAdd(&g_s2[(bm + tid) * 4 + h], s2b[tid]);
    }
}

// ---------------- edge kernels ----------------------------------------------
__global__ void hist_kernel(const void* __restrict__ edge) {
    int e = blockIdx.x * blockDim.x + threadIdx.x;
    if (e >= EE) return;
    int src = load_edge(edge, e);
    atomicAdd(&g_deg[src], 1);
}

// 196-block atomic-offset allocator (4.7us measured).
__global__ __launch_bounds__(256) void offset_kernel() {
    __shared__ int wsum[8];
    __shared__ int sbase;
    const int tid = threadIdx.x, lane = tid & 31, wd = tid >> 5;
    const int n = blockIdx.x * 256 + tid;
    int d = (n < NN) ? g_deg[n] : 0;
    int v = d;
#pragma unroll
    for (int o = 1; o < 32; o <<= 1) {
        int u = __shfl_up_sync(0xffffffffu, v, o);
        if (lane >= o) v += u;
    }
    if (lane == 31) wsum[wd] = v;
    __syncthreads();
    if (tid == 0) {
        int run = 0;
#pragma unroll
        for (int i = 0; i < 8; i++) { int t = wsum[i]; wsum[i] = run; run += t; }
        sbase = atomicAdd(&g_alloc, run);
    }
    __syncthreads();
    int beg = sbase + wsum[wd] + v - d;   // exclusive prefix + block base
    if (n < NN) { g_rowbeg[n] = beg; g_cursor[n] = beg; }
}

__global__ __launch_bounds__(256) void score_scatter_kernel(const void* __restrict__ edge) {
    int e = blockIdx.x * blockDim.x + threadIdx.x;
    if (e >= EE) return;
    int src = load_edge(edge, e);
    int dst = load_edge(edge, (long long)EE + e);
    float4 v1 = *reinterpret_cast<const float4*>(g_s1 + src * 4);
    float4 v2 = *reinterpret_cast<const float4*>(g_s2 + dst * 4);
    float4 sc;
    {
        float s0 = v1.x + v2.x, s1 = v1.y + v2.y, s2 = v1.z + v2.z, s3 = v1.w + v2.w;
        s0 = (s0 >= 0.f ? s0 : ALPHA_L * s0) * INV_SCALE;
        s1 = (s1 >= 0.f ? s1 : ALPHA_L * s1) * INV_SCALE;
        s2 = (s2 >= 0.f ? s2 : ALPHA_L * s2) * INV_SCALE;
        s3 = (s3 >= 0.f ? s3 : ALPHA_L * s3) * INV_SCALE;
        sc = make_float4(__expf(s0), __expf(s1), __expf(s2), __expf(s3));
    }
    int pos = atomicAdd(&g_cursor[src], 1);
    g_dsts[pos] = dst;
    g_es[pos]   = sc;
}

// One block (128 thr) per node: two 64-thread edge-teams, uint4 gathers.
// Thread q owns cols 8q..8q+7 (single head, since 8 | 128). Team p handles
// edges beg+p, beg+p+2, ... Partial sums merge through smem, then LN+ELU.
__global__ __launch_bounds__(128) void agg_ln_kernel(
    const float* __restrict__ gain, const float* __restrict__ beta,
    float* __restrict__ out)
{
    __shared__ float sacc[64][9];    // team-1 partial accs (pad 9 vs bank)
    __shared__ float sr[4];          // team-1 rowsums
    __shared__ float red[4];         // LN cross-warp scratch
    __shared__ float bc[2];          // mean, inv broadcast

    const int n = blockIdx.x;
    const int t = threadIdx.x;
    const int team = t >> 6;
    const int q = t & 63;
    const int head = q >> 4;
    const int beg = g_rowbeg[n], end = beg + g_deg[n];

    float acc[8];
#pragma unroll
    for (int j = 0; j < 8; j++) acc[j] = 0.f;
    float r0 = 0.f, r1 = 0.f, r2 = 0.f, r3 = 0.f;

    int i = beg + team;
    int d = 0; float4 e = make_float4(0.f, 0.f, 0.f, 0.f);
    if (i < end) { d = __ldcs(&g_dsts[i]); e = __ldcs(&g_es[i]); }
    for (; i < end; i += 2) {
        int dn = 0; float4 en = make_float4(0.f, 0.f, 0.f, 0.f);
        if (i + 2 < end) { dn = __ldcs(&g_dsts[i + 2]); en = __ldcs(&g_es[i + 2]); }
        const uint4* xr = reinterpret_cast<const uint4*>(g_Xh + (size_t)d * COLS);
        uint4 v = xr[q];                                  // 8 halfs, cols 8q..
        float w = head == 0 ? e.x : head == 1 ? e.y : head == 2 ? e.z : e.w;
        float2 f;
        f = __half22float2(*reinterpret_cast<__half2*>(&v.x));
        acc[0] = fmaf(w, f.x, acc[0]); acc[1] = fmaf(w, f.y, acc[1]);
        f = __half22float2(*reinterpret_cast<__half2*>(&v.y));
        acc[2] = fmaf(w, f.x, acc[2]); acc[3] = fmaf(w, f.y, acc[3]);
        f = __half22float2(*reinterpret_cast<__half2*>(&v.z));
        acc[4] = fmaf(w, f.x, acc[4]); acc[5] = fmaf(w, f.y, acc[5]);
        f = __half22float2(*reinterpret_cast<__half2*>(&v.w));
        acc[6] = fmaf(w, f.x, acc[6]); acc[7] = fmaf(w, f.y, acc[7]);
        r0 += e.x; r1 += e.y; r2 += e.z; r3 += e.w;
        d = dn; e = en;
    }

    // merge team 1 into team 0
    if (team == 1) {
#pragma unroll
        for (int j = 0; j < 8; j++) sacc[q][j] = acc[j];
        if (q == 0) { sr[0] = r0; sr[1] = r1; sr[2] = r2; sr[3] = r3; }
    }
    __syncthreads();
    if (team == 1) return;     // team 0 finishes LN + output

#pragma unroll
    for (int j = 0; j < 8; j++) acc[j] += sacc[q][j];
    r0 += sr[0]; r1 += sr[1]; r2 += sr[2]; r3 += sr[3];

    float den = head == 0 ? r0 : head == 1 ? r1 : head == 2 ? r2 : r3;
    den = (den == 0.f) ? 1.f : den;
    float inv_d = 1.f / den;
    float h[8];
    float s = 0.f, ss = 0.f;
#pragma unroll
    for (int j = 0; j < 8; j++) {
        h[j] = acc[j] * inv_d;
        s += h[j];
        ss = fmaf(h[j], h[j], ss);
    }
#pragma unroll
    for (int o = 16; o; o >>= 1) {
        s  += __shfl_xor_sync(0xffffffffu, s, o);
        ss += __shfl_xor_sync(0xffffffffu, ss, o);
    }
    int w32 = q >> 5;
    if ((q & 31) == 0) { red[w32] = s; red[2 + w32] = ss; }
    __syncthreads();
    if (q == 0) {
        float S = red[0] + red[1], SS = red[2] + red[3];
        float mean = S * (1.f / 512.f);
        float var  = fmaxf((SS - 512.f * mean * mean) * (1.f / 511.f), 0.f);
        bc[0] = mean;
        bc[1] = 1.f / (sqrtf(var) + LN_EPS);
    }
    __syncthreads();
    float mean = bc[0], inv = bc[1];

    float* orow = out + (size_t)n * COLS;
    float o0[8];
#pragma unroll
    for (int j = 0; j < 8; j++) {
        int c = 8 * q + j;
        float v = gain[c] * (h[j] - mean) * inv + beta[c];
        o0[j] = v > 0.f ? v : expm1f(v);
    }
    *reinterpret_cast<float4*>(orow + 8 * q)     = make_float4(o0[0], o0[1], o0[2], o0[3]);
    *reinterpret_cast<float4*>(orow + 8 * q + 4) = make_float4(o0[4], o0[5], o0[6], o0[7]);
}

// ---------------- launch -----------------------------------------------------
extern "C" void kernel_launch(void* const* d_in, const int* in_sizes, int n_in,
                              void* d_out, int out_size)
{
    (void)in_sizes; (void)n_in; (void)out_size;
    const void*  edge   = d_in[1];
    const float* emb    = (const float*)d_in[2];
    const float* W      = (const float*)d_in[3];
    const float* bias   = (const float*)d_in[4];
    const float* a_attn = (const float*)d_in[5];
    const float* gain   = (const float*)d_in[6];
    const float* beta   = (const float*)d_in[7];
    float* out = (float*)d_out;

    prep_kernel<<<PREP_A_BLOCKS, 256>>>(emb, W, (const int*)edge);

    dim3 gg(M_TILES, 8);
    gemm_mma_kernel<<<gg, 256>>>(bias, a_attn);

    hist_kernel<<<(EE + 255) / 256, 256>>>(edge);
    offset_kernel<<<OFF_BLOCKS, 256>>>();
    score_scatter_kernel<<<(EE + 255) / 256, 256>>>(edge);

    agg_ln_kernel<<<NN, 128>>>(gain, beta, out);
}